// round 8
// baseline (speedup 1.0000x reference)
#include <cuda_runtime.h>

#define LRES 1024
#define TOPK 48
#define EF   416
#define SF   1280
#define KT   16
#define NTILE 3
#define WP   130   // Wsm2 pitch in ull (even -> 16B-aligned ulonglong2 loads)

#define OFF_E       0ull
#define OFF_EIDX    6291456ull
#define OFF_ES      6340608ull
#define OFF_EIDXSUB 12632064ull

__device__ float g_coords[LRES * 15];
__device__ int   g_eidx[LRES * TOPK];
__device__ float g_dnb[LRES * TOPK];

__device__ __forceinline__ unsigned long long u64min_(unsigned long long a,
                                                      unsigned long long b) {
    return a < b ? a : b;
}

__device__ __forceinline__ unsigned long long fma2(unsigned long long a,
                                                   unsigned long long b,
                                                   unsigned long long c) {
    unsigned long long d;
    asm("fma.rn.f32x2 %0, %1, %2, %3;" : "=l"(d) : "l"(a), "l"(b), "l"(c));
    return d;
}

__device__ __forceinline__ float pairsum(unsigned long long v) {
    float lo, hi;
    asm("mov.b64 {%0, %1}, %2;" : "=f"(lo), "=f"(hi) : "l"(v));
    return lo + hi;
}

// Chained RBF (2 expf instead of NB), guarded reverse chain vs underflow.
template <int NB>
__device__ __forceinline__ void rbf_gen(float D, float m, float* __restrict__ fr,
                                        float SINV, float D2, float E2c) {
    float s = (D - 2.0f) * SINV;
    float v = __expf(-D2 * s * s);
    float g = __expf(D2 * (2.0f * s - 1.0f));
    float vals[NB];
    vals[0] = v;
    #pragma unroll
    for (int r = 1; r < NB; r++) { v *= g; g *= E2c; vals[r] = v; }
    if (vals[0] < 1e-30f) {
        float sN = s - (float)(NB - 1);
        float v1 = __expf(-D2 * sN * sN);
        float g1 = __expf(-D2 * (2.0f * sN + 1.0f));
        vals[NB - 1] = fmaxf(vals[NB - 1], v1);
        #pragma unroll
        for (int r = NB - 2; r >= 0; r--) {
            v1 *= g1; g1 *= E2c;
            vals[r] = fmaxf(vals[r], v1);
        }
    }
    #pragma unroll
    for (int r = 0; r < NB; r++) fr[r] = m * vals[r];
}

#define E_SINV 0.75f
#define E_D2   1.13777778f
#define E_E2   0.10273980f
#define S_SINV 0.35f
#define S_D2   1.30612245f
#define S_E2   0.07336966f

// Stage 128ch x 32feat tile into Wsm2[f2*WP + ch] (ull = packed (2f2,2f2+1)).
__device__ __forceinline__ void stage_w(const float* __restrict__ W, int stride,
                                        int f0, unsigned long long* Wsm2,
                                        int tid) {
    #pragma unroll
    for (int p = tid; p < 2048; p += 256) {
        int o = p >> 4, f2 = p & 15;
        float2 v = *(const float2*)(W + (size_t)o * stride + f0 + 2 * f2);
        unsigned long long u;
        asm("mov.b64 %0, {%1, %2};" : "=l"(u) : "f"(v.x), "f"(v.y));
        Wsm2[f2 * WP + o] = u;
    }
}

// ---------------------------------------------------------------------------
__global__ void geom_kernel(const float* __restrict__ X) {
    int i = blockIdx.x * blockDim.x + threadIdx.x;
    if (i >= LRES) return;
    const float* xi = X + (size_t)i * 37 * 3;
    float n0 = xi[0],  n1 = xi[1],  n2 = xi[2];
    float a0 = xi[3],  a1 = xi[4],  a2 = xi[5];
    float c0 = xi[6],  c1 = xi[7],  c2 = xi[8];
    float o0 = xi[12], o1 = xi[13], o2 = xi[14];
    float b0 = a0 - n0, b1 = a1 - n1, b2 = a2 - n2;
    float d0 = c0 - a0, d1 = c1 - a1, d2 = c2 - a2;
    float x0 = b1 * d2 - b2 * d1;
    float x1 = b2 * d0 - b0 * d2;
    float x2 = b0 * d1 - b1 * d0;
    float cb0 = -0.58273431f * x0 + 0.56802827f * b0 - 0.54067466f * d0 + a0;
    float cb1 = -0.58273431f * x1 + 0.56802827f * b1 - 0.54067466f * d1 + a1;
    float cb2 = -0.58273431f * x2 + 0.56802827f * b2 - 0.54067466f * d2 + a2;
    float* dst = g_coords + i * 15;
    dst[0] = n0;  dst[1] = n1;  dst[2] = n2;
    dst[3] = a0;  dst[4] = a1;  dst[5] = a2;
    dst[6] = c0;  dst[7] = c1;  dst[8] = c2;
    dst[9] = o0;  dst[10] = o1; dst[11] = o2;
    dst[12] = cb0; dst[13] = cb1; dst[14] = cb2;
}

// ---------------------------------------------------------------------------
__global__ void topk_kernel(const float* __restrict__ X,
                            const float* __restrict__ mask,
                            float* __restrict__ out) {
    __shared__ float dsh[LRES];
    __shared__ unsigned long long keys[LRES];
    __shared__ float wmaxs[8];
    __shared__ unsigned long long wmins[8];
    __shared__ float smDmax;

    int i = blockIdx.x;
    int tid = threadIdx.x;
    float cax = X[((size_t)i * 37 + 1) * 3 + 0];
    float cay = X[((size_t)i * 37 + 1) * 3 + 1];
    float caz = X[((size_t)i * 37 + 1) * 3 + 2];
    float mi = mask[i];

    float lmax = 0.0f;
    for (int j = tid; j < LRES; j += 256) {
        float dx = cax - X[((size_t)j * 37 + 1) * 3 + 0];
        float dy = cay - X[((size_t)j * 37 + 1) * 3 + 1];
        float dz = caz - X[((size_t)j * 37 + 1) * 3 + 2];
        float s = dx * dx + dy * dy + dz * dz;
        float m2 = mi * mask[j];
        float Dv = m2 * sqrtf(s + 1e-6f);
        dsh[j] = Dv;
        lmax = fmaxf(lmax, Dv);
    }
    for (int off = 16; off; off >>= 1)
        lmax = fmaxf(lmax, __shfl_xor_sync(0xffffffffu, lmax, off));
    if ((tid & 31) == 0) wmaxs[tid >> 5] = lmax;
    __syncthreads();
    if (tid == 0) {
        float m = wmaxs[0];
        #pragma unroll
        for (int w = 1; w < 8; w++) m = fmaxf(m, wmaxs[w]);
        smDmax = m;
    }
    __syncthreads();
    float Dmax = smDmax;

    for (int j = tid; j < LRES; j += 256) {
        float m2 = mi * mask[j];
        float Dadj = dsh[j] + (1.0f - m2) * Dmax;
        keys[j] = (((unsigned long long)__float_as_uint(Dadj)) << 32) |
                  (unsigned int)j;
    }
    __syncthreads();

    for (int sel = 0; sel < TOPK; sel++) {
        unsigned long long lmin = 0xffffffffffffffffull;
        #pragma unroll
        for (int c = 0; c < 4; c++) lmin = u64min_(lmin, keys[tid + 256 * c]);
        for (int off = 16; off; off >>= 1) {
            unsigned long long o2 = __shfl_xor_sync(0xffffffffu, lmin, off);
            lmin = u64min_(lmin, o2);
        }
        if ((tid & 31) == 0) wmins[tid >> 5] = lmin;
        __syncthreads();
        if (tid == 0) {
            unsigned long long m = wmins[0];
            #pragma unroll
            for (int w = 1; w < 8; w++) m = u64min_(m, wmins[w]);
            int j = (int)(m & 0xffffffffull);
            float dv = __uint_as_float((unsigned int)(m >> 32));
            g_eidx[i * TOPK + sel] = j;
            g_dnb[i * TOPK + sel] = dv;
            out[OFF_EIDX + (size_t)i * TOPK + sel] = (float)j;
            out[OFF_EIDXSUB + (size_t)i * TOPK + sel] = (float)j;
            keys[j] = 0xffffffffffffffffull;
        }
        __syncthreads();
    }
}

// ---------------------------------------------------------------------------
// Kernel 3: E. 256 threads, warp = (edge-group[4] x 12 edges, ch-half[2]).
// Double-buffered W staging.
// ---------------------------------------------------------------------------
__global__ void __launch_bounds__(256, 2) e_kernel(
    const float* __restrict__ Wpos, const float* __restrict__ bpos,
    const int* __restrict__ ridx, const int* __restrict__ clab,
    const float* __restrict__ We, const float* __restrict__ ge,
    const float* __restrict__ be, float* __restrict__ out) {
    extern __shared__ float feats[];  // 48*416 floats, then 2x Wsm2[16*WP]
    unsigned long long* Wbuf0 = (unsigned long long*)(feats + TOPK * EF);
    unsigned long long* Wbuf1 = Wbuf0 + 16 * WP;
    int i = blockIdx.x;
    int tid = threadIdx.x;
    int wid = tid >> 5, lane = tid & 31;

    if (tid < TOPK) {
        int k = tid;
        int j = g_eidx[i * TOPK + k];
        int offr = ridx[i] - ridx[j];
        int ec = (clab[i] == clab[j]) ? 1 : 0;
        int d = min(max(offr + 32, 0), 64) * ec + (1 - ec) * 65;
        float* fr = feats + k * EF;
        #pragma unroll
        for (int f = 0; f < 16; f++) fr[f] = Wpos[f * 66 + d] + bpos[f];
        rbf_gen<16>(g_dnb[i * TOPK + k], 1.0f, fr + 16, E_SINV, E_D2, E_E2);
    }

    const signed char pa[24] = {0,2,3,4,1,1,1,1,0,0,0,4,4,3,0,2,3,4,2,3,4,2,3,2};
    const signed char pb[24] = {0,2,3,4,0,2,3,4,2,3,4,2,3,2,1,1,1,1,0,0,0,4,4,3};
    for (int tt = tid; tt < TOPK * 24; tt += 256) {
        int k = tt / 24, p = tt - k * 24;
        int j = g_eidx[i * TOPK + k];
        const float* A = g_coords + i * 15 + (int)pa[p] * 3;
        const float* B = g_coords + j * 15 + (int)pb[p] * 3;
        float dx = A[0] - B[0], dy = A[1] - B[1], dz = A[2] - B[2];
        float D = sqrtf(dx * dx + dy * dy + dz * dz + 1e-6f);
        rbf_gen<16>(D, 1.0f, feats + k * EF + 32 + p * 16, E_SINV, E_D2, E_E2);
    }

    int eg = wid >> 1;
    int chh = wid & 1;
    int op = chh * 64 + 2 * lane;
    unsigned long long acc0[12], acc1[12];
    #pragma unroll
    for (int k = 0; k < 12; k++) { acc0[k] = 0ull; acc1[k] = 0ull; }

    stage_w(We, EF, 0, Wbuf0, tid);
    __syncthreads();
    for (int st = 0; st < EF / 32; st++) {
        unsigned long long* Wcur = (st & 1) ? Wbuf1 : Wbuf0;
        if (st + 1 < EF / 32) {
            unsigned long long* Wnxt = (st & 1) ? Wbuf0 : Wbuf1;
            stage_w(We, EF, (st + 1) * 32, Wnxt, tid);
        }
        const float* fb = feats + st * 32;
        #pragma unroll
        for (int q = 0; q < 8; q++) {
            ulonglong2 wa = *(const ulonglong2*)(Wcur + (2 * q) * WP + op);
            ulonglong2 wb = *(const ulonglong2*)(Wcur + (2 * q + 1) * WP + op);
            #pragma unroll
            for (int k = 0; k < 12; k++) {
                ulonglong2 v = *(const ulonglong2*)(fb + (eg * 12 + k) * EF + 4 * q);
                acc0[k] = fma2(wa.x, v.x, acc0[k]);
                acc0[k] = fma2(wb.x, v.y, acc0[k]);
                acc1[k] = fma2(wa.y, v.x, acc1[k]);
                acc1[k] = fma2(wb.y, v.y, acc1[k]);
            }
        }
        __syncthreads();
    }

    float* h = feats;  // 48*128
    #pragma unroll
    for (int k = 0; k < 12; k++) {
        h[(eg * 12 + k) * 128 + op] = pairsum(acc0[k]);
        h[(eg * 12 + k) * 128 + op + 1] = pairsum(acc1[k]);
    }
    __syncthreads();

    for (int k = wid; k < TOPK; k += 8) {
        float v0 = h[k * 128 + lane];
        float v1 = h[k * 128 + lane + 32];
        float v2 = h[k * 128 + lane + 64];
        float v3 = h[k * 128 + lane + 96];
        float s = v0 + v1 + v2 + v3;
        for (int off = 16; off; off >>= 1) s += __shfl_xor_sync(0xffffffffu, s, off);
        float mu = s * (1.0f / 128.0f);
        float d0 = v0 - mu, d1 = v1 - mu, d2 = v2 - mu, d3 = v3 - mu;
        float s2 = d0 * d0 + d1 * d1 + d2 * d2 + d3 * d3;
        for (int off = 16; off; off >>= 1) s2 += __shfl_xor_sync(0xffffffffu, s2, off);
        float inv = rsqrtf(s2 * (1.0f / 128.0f) + 1e-5f);
        size_t base = OFF_E + ((size_t)(i * TOPK + k)) * 128;
        out[base + lane]      = ge[lane]      * d0 * inv + be[lane];
        out[base + lane + 32] = ge[lane + 32] * d1 * inv + be[lane + 32];
        out[base + lane + 64] = ge[lane + 64] * d2 * inv + be[lane + 64];
        out[base + lane + 96] = ge[lane + 96] * d3 * inv + be[lane + 96];
    }
}

// ---------------------------------------------------------------------------
// Kernel 4: E_s. 256 threads, warp = (ch-half[2], feat-quarter[4]); every warp
// owns all 16 edges. Double-buffered W staging; 4-way fh combine in smem.
// ---------------------------------------------------------------------------
__global__ void __launch_bounds__(256, 2) es_kernel(
    const float* __restrict__ X, const float* __restrict__ amask,
    const float* __restrict__ Ws, const float* __restrict__ gs,
    const float* __restrict__ bs, float* __restrict__ out) {
    extern __shared__ float feats[];  // 16*1280 floats, then 2x Wsm2[16*WP]
    unsigned long long* Wbuf0 = (unsigned long long*)(feats + KT * SF);
    unsigned long long* Wbuf1 = Wbuf0 + 16 * WP;
    __shared__ int jn[KT];
    __shared__ float anch[15];

    int bx = blockIdx.x;
    int i = bx / NTILE;
    int k0 = (bx - i * NTILE) * KT;
    int tid = threadIdx.x;
    int wid = tid >> 5, lane = tid & 31;

    if (tid < KT) jn[tid] = g_eidx[i * TOPK + k0 + tid];
    if (tid >= 32 && tid < 47) anch[tid - 32] = g_coords[i * 15 + (tid - 32)];
    __syncthreads();

    for (int tt = tid; tt < KT * 160; tt += 256) {
        int kk = tt / 160;
        int rem = tt - kk * 160;
        int a = rem >> 5, s = rem & 31;
        int j = jn[kk];
        const float* Sp = X + ((size_t)j * 37 + 5 + s) * 3;
        float dx = anch[a * 3 + 0] - Sp[0];
        float dy = anch[a * 3 + 1] - Sp[1];
        float dz = anch[a * 3 + 2] - Sp[2];
        float D = sqrtf(dx * dx + dy * dy + dz * dz + 1e-6f);
        float m = amask[(size_t)j * 37 + 5 + s];
        rbf_gen<8>(D, m, feats + kk * SF + (a * 32 + s) * 8, S_SINV, S_D2, S_E2);
    }

    int chh = wid & 1;       // channel half
    int fh = wid >> 1;       // feature quarter (8 feats per 32-stage)
    int op = chh * 64 + 2 * lane;
    unsigned long long acc0[KT], acc1[KT];
    #pragma unroll
    for (int k = 0; k < KT; k++) { acc0[k] = 0ull; acc1[k] = 0ull; }

    stage_w(Ws, SF, 0, Wbuf0, tid);
    __syncthreads();
    for (int st = 0; st < SF / 32; st++) {
        unsigned long long* Wcur = (st & 1) ? Wbuf1 : Wbuf0;
        if (st + 1 < SF / 32) {
            unsigned long long* Wnxt = (st & 1) ? Wbuf0 : Wbuf1;
            stage_w(Ws, SF, (st + 1) * 32, Wnxt, tid);
        }
        const float* fb = feats + st * 32 + fh * 8;
        #pragma unroll
        for (int q = 0; q < 2; q++) {
            int f2a = fh * 4 + 2 * q;
            ulonglong2 wa = *(const ulonglong2*)(Wcur + f2a * WP + op);
            ulonglong2 wb = *(const ulonglong2*)(Wcur + (f2a + 1) * WP + op);
            #pragma unroll
            for (int k = 0; k < KT; k++) {
                ulonglong2 v = *(const ulonglong2*)(fb + k * SF + 4 * q);
                acc0[k] = fma2(wa.x, v.x, acc0[k]);
                acc0[k] = fma2(wb.x, v.y, acc0[k]);
                acc1[k] = fma2(wa.y, v.x, acc1[k]);
                acc1[k] = fma2(wb.y, v.y, acc1[k]);
            }
        }
        __syncthreads();
    }

    float* h = feats;  // 16*128
    if (fh == 0) {
        #pragma unroll
        for (int k = 0; k < KT; k++) {
            h[k * 128 + op] = pairsum(acc0[k]);
            h[k * 128 + op + 1] = pairsum(acc1[k]);
        }
    }
    __syncthreads();
    #pragma unroll
    for (int f = 1; f < 4; f++) {
        if (fh == f) {
            #pragma unroll
            for (int k = 0; k < KT; k++) {
                h[k * 128 + op] += pairsum(acc0[k]);
                h[k * 128 + op + 1] += pairsum(acc1[k]);
            }
        }
        __syncthreads();
    }

    for (int kk = wid; kk < KT; kk += 8) {
        float v0 = h[kk * 128 + lane];
        float v1 = h[kk * 128 + lane + 32];
        float v2 = h[kk * 128 + lane + 64];
        float v3 = h[kk * 128 + lane + 96];
        float s = v0 + v1 + v2 + v3;
        for (int off = 16; off; off >>= 1) s += __shfl_xor_sync(0xffffffffu, s, off);
        float mu = s * (1.0f / 128.0f);
        float d0 = v0 - mu, d1 = v1 - mu, d2 = v2 - mu, d3 = v3 - mu;
        float s2 = d0 * d0 + d1 * d1 + d2 * d2 + d3 * d3;
        for (int off = 16; off; off >>= 1) s2 += __shfl_xor_sync(0xffffffffu, s2, off);
        float inv = rsqrtf(s2 * (1.0f / 128.0f) + 1e-5f);
        size_t base = OFF_ES + ((size_t)(i * TOPK + k0 + kk)) * 128;
        out[base + lane]      = gs[lane]      * d0 * inv + bs[lane];
        out[base + lane + 32] = gs[lane + 32] * d1 * inv + bs[lane + 32];
        out[base + lane + 64] = gs[lane + 64] * d2 * inv + bs[lane + 64];
        out[base + lane + 96] = gs[lane + 96] * d3 * inv + bs[lane + 96];
    }
}

// ---------------------------------------------------------------------------
extern "C" void kernel_launch(void* const* d_in, const int* in_sizes, int n_in,
                              void* d_out, int out_size) {
    (void)in_sizes; (void)n_in; (void)out_size;
    const float* X     = (const float*)d_in[0];
    const float* mask  = (const float*)d_in[2];
    const float* amask = (const float*)d_in[3];
    const int*   ridx  = (const int*)d_in[4];
    const int*   clab  = (const int*)d_in[6];
    const float* Wpos  = (const float*)d_in[7];
    const float* bpos  = (const float*)d_in[8];
    const float* We    = (const float*)d_in[9];
    const float* ge    = (const float*)d_in[10];
    const float* be    = (const float*)d_in[11];
    const float* Ws    = (const float*)d_in[12];
    const float* gs    = (const float*)d_in[13];
    const float* bs    = (const float*)d_in[14];
    float* out = (float*)d_out;

    int e_smem  = TOPK * EF * 4 + 2 * 16 * WP * 8;   // 79872 + 33280 = 113152
    int es_smem = KT * SF * 4 + 2 * 16 * WP * 8;     // 81920 + 33280 = 115200
    cudaFuncSetAttribute(e_kernel, cudaFuncAttributeMaxDynamicSharedMemorySize,
                         e_smem);
    cudaFuncSetAttribute(es_kernel, cudaFuncAttributeMaxDynamicSharedMemorySize,
                         es_smem);

    geom_kernel<<<(LRES + 255) / 256, 256>>>(X);
    topk_kernel<<<LRES, 256>>>(X, mask, out);
    e_kernel<<<LRES, 256, e_smem>>>(Wpos, bpos, ridx, clab, We, ge, be, out);
    es_kernel<<<LRES * NTILE, 256, es_smem>>>(X, amask, Ws, gs, bs, out);
}

// round 9
// speedup vs baseline: 1.0686x; 1.0686x over previous
#include <cuda_runtime.h>

#define LRES 1024
#define TOPK 48
#define EF   416
#define SF   1280
#define KT   16
#define NTILE 3
#define WP   130   // Wsm2 pitch in ull (even -> 16B-aligned ulonglong2 loads)

#define OFF_E       0ull
#define OFF_EIDX    6291456ull
#define OFF_ES      6340608ull
#define OFF_EIDXSUB 12632064ull

__device__ float g_coords[LRES * 15];
__device__ int   g_eidx[LRES * TOPK];
__device__ float g_dnb[LRES * TOPK];

__device__ __forceinline__ unsigned long long u64min_(unsigned long long a,
                                                      unsigned long long b) {
    return a < b ? a : b;
}

__device__ __forceinline__ unsigned long long fma2(unsigned long long a,
                                                   unsigned long long b,
                                                   unsigned long long c) {
    unsigned long long d;
    asm("fma.rn.f32x2 %0, %1, %2, %3;" : "=l"(d) : "l"(a), "l"(b), "l"(c));
    return d;
}

__device__ __forceinline__ float pairsum(unsigned long long v) {
    float lo, hi;
    asm("mov.b64 {%0, %1}, %2;" : "=f"(lo), "=f"(hi) : "l"(v));
    return lo + hi;
}

__device__ __forceinline__ void cp_commit() {
    asm volatile("cp.async.commit_group;" ::: "memory");
}
__device__ __forceinline__ void cp_wait0() {
    asm volatile("cp.async.wait_group 0;" ::: "memory");
}

// Chained RBF (2 expf instead of NB), guarded reverse chain vs underflow.
template <int NB>
__device__ __forceinline__ void rbf_gen(float D, float m, float* __restrict__ fr,
                                        float SINV, float D2, float E2c) {
    float s = (D - 2.0f) * SINV;
    float v = __expf(-D2 * s * s);
    float g = __expf(D2 * (2.0f * s - 1.0f));
    float vals[NB];
    vals[0] = v;
    #pragma unroll
    for (int r = 1; r < NB; r++) { v *= g; g *= E2c; vals[r] = v; }
    if (vals[0] < 1e-30f) {
        float sN = s - (float)(NB - 1);
        float v1 = __expf(-D2 * sN * sN);
        float g1 = __expf(-D2 * (2.0f * sN + 1.0f));
        vals[NB - 1] = fmaxf(vals[NB - 1], v1);
        #pragma unroll
        for (int r = NB - 2; r >= 0; r--) {
            v1 *= g1; g1 *= E2c;
            vals[r] = fmaxf(vals[r], v1);
        }
    }
    #pragma unroll
    for (int r = 0; r < NB; r++) fr[r] = m * vals[r];
}

#define E_SINV 0.75f
#define E_D2   1.13777778f
#define E_E2   0.10273980f
#define S_SINV 0.35f
#define S_D2   1.30612245f
#define S_E2   0.07336966f

// Async-stage 128ch x 32feat tile into Wsm2[f2*WP + ch] via cp.async (8B).
__device__ __forceinline__ void stage_w_async(const float* __restrict__ W,
                                              int stride, int f0,
                                              unsigned long long* Wsm2,
                                              int tid) {
    #pragma unroll
    for (int p = tid; p < 2048; p += 256) {
        int o = p >> 4, f2 = p & 15;
        const float* src = W + (size_t)o * stride + f0 + 2 * f2;
        unsigned int dst =
            (unsigned int)__cvta_generic_to_shared(Wsm2 + f2 * WP + o);
        asm volatile("cp.async.ca.shared.global [%0], [%1], 8;"
                     :: "r"(dst), "l"(src) : "memory");
    }
}

// ---------------------------------------------------------------------------
__global__ void geom_kernel(const float* __restrict__ X) {
    int i = blockIdx.x * blockDim.x + threadIdx.x;
    if (i >= LRES) return;
    const float* xi = X + (size_t)i * 37 * 3;
    float n0 = xi[0],  n1 = xi[1],  n2 = xi[2];
    float a0 = xi[3],  a1 = xi[4],  a2 = xi[5];
    float c0 = xi[6],  c1 = xi[7],  c2 = xi[8];
    float o0 = xi[12], o1 = xi[13], o2 = xi[14];
    float b0 = a0 - n0, b1 = a1 - n1, b2 = a2 - n2;
    float d0 = c0 - a0, d1 = c1 - a1, d2 = c2 - a2;
    float x0 = b1 * d2 - b2 * d1;
    float x1 = b2 * d0 - b0 * d2;
    float x2 = b0 * d1 - b1 * d0;
    float cb0 = -0.58273431f * x0 + 0.56802827f * b0 - 0.54067466f * d0 + a0;
    float cb1 = -0.58273431f * x1 + 0.56802827f * b1 - 0.54067466f * d1 + a1;
    float cb2 = -0.58273431f * x2 + 0.56802827f * b2 - 0.54067466f * d2 + a2;
    float* dst = g_coords + i * 15;
    dst[0] = n0;  dst[1] = n1;  dst[2] = n2;
    dst[3] = a0;  dst[4] = a1;  dst[5] = a2;
    dst[6] = c0;  dst[7] = c1;  dst[8] = c2;
    dst[9] = o0;  dst[10] = o1; dst[11] = o2;
    dst[12] = cb0; dst[13] = cb1; dst[14] = cb2;
}

// ---------------------------------------------------------------------------
__global__ void topk_kernel(const float* __restrict__ X,
                            const float* __restrict__ mask,
                            float* __restrict__ out) {
    __shared__ float dsh[LRES];
    __shared__ unsigned long long keys[LRES];
    __shared__ float wmaxs[8];
    __shared__ unsigned long long wmins[8];
    __shared__ float smDmax;

    int i = blockIdx.x;
    int tid = threadIdx.x;
    float cax = X[((size_t)i * 37 + 1) * 3 + 0];
    float cay = X[((size_t)i * 37 + 1) * 3 + 1];
    float caz = X[((size_t)i * 37 + 1) * 3 + 2];
    float mi = mask[i];

    float lmax = 0.0f;
    for (int j = tid; j < LRES; j += 256) {
        float dx = cax - X[((size_t)j * 37 + 1) * 3 + 0];
        float dy = cay - X[((size_t)j * 37 + 1) * 3 + 1];
        float dz = caz - X[((size_t)j * 37 + 1) * 3 + 2];
        float s = dx * dx + dy * dy + dz * dz;
        float m2 = mi * mask[j];
        float Dv = m2 * sqrtf(s + 1e-6f);
        dsh[j] = Dv;
        lmax = fmaxf(lmax, Dv);
    }
    for (int off = 16; off; off >>= 1)
        lmax = fmaxf(lmax, __shfl_xor_sync(0xffffffffu, lmax, off));
    if ((tid & 31) == 0) wmaxs[tid >> 5] = lmax;
    __syncthreads();
    if (tid == 0) {
        float m = wmaxs[0];
        #pragma unroll
        for (int w = 1; w < 8; w++) m = fmaxf(m, wmaxs[w]);
        smDmax = m;
    }
    __syncthreads();
    float Dmax = smDmax;

    for (int j = tid; j < LRES; j += 256) {
        float m2 = mi * mask[j];
        float Dadj = dsh[j] + (1.0f - m2) * Dmax;
        keys[j] = (((unsigned long long)__float_as_uint(Dadj)) << 32) |
                  (unsigned int)j;
    }
    __syncthreads();

    for (int sel = 0; sel < TOPK; sel++) {
        unsigned long long lmin = 0xffffffffffffffffull;
        #pragma unroll
        for (int c = 0; c < 4; c++) lmin = u64min_(lmin, keys[tid + 256 * c]);
        for (int off = 16; off; off >>= 1) {
            unsigned long long o2 = __shfl_xor_sync(0xffffffffu, lmin, off);
            lmin = u64min_(lmin, o2);
        }
        if ((tid & 31) == 0) wmins[tid >> 5] = lmin;
        __syncthreads();
        if (tid == 0) {
            unsigned long long m = wmins[0];
            #pragma unroll
            for (int w = 1; w < 8; w++) m = u64min_(m, wmins[w]);
            int j = (int)(m & 0xffffffffull);
            float dv = __uint_as_float((unsigned int)(m >> 32));
            g_eidx[i * TOPK + sel] = j;
            g_dnb[i * TOPK + sel] = dv;
            out[OFF_EIDX + (size_t)i * TOPK + sel] = (float)j;
            out[OFF_EIDXSUB + (size_t)i * TOPK + sel] = (float)j;
            keys[j] = 0xffffffffffffffffull;
        }
        __syncthreads();
    }
}

// ---------------------------------------------------------------------------
// Kernel 3: E. 256 threads, warp = (edge-group[4] x 12 edges, ch-half[2]).
// cp.async double-buffered W staging, 1 barrier per stage.
// ---------------------------------------------------------------------------
__global__ void __launch_bounds__(256, 2) e_kernel(
    const float* __restrict__ Wpos, const float* __restrict__ bpos,
    const int* __restrict__ ridx, const int* __restrict__ clab,
    const float* __restrict__ We, const float* __restrict__ ge,
    const float* __restrict__ be, float* __restrict__ out) {
    extern __shared__ float feats[];  // 48*416 floats, then 2x Wsm2[16*WP]
    unsigned long long* Wbuf0 = (unsigned long long*)(feats + TOPK * EF);
    unsigned long long* Wbuf1 = Wbuf0 + 16 * WP;
    int i = blockIdx.x;
    int tid = threadIdx.x;
    int wid = tid >> 5, lane = tid & 31;

    // start stage 0 load immediately (overlaps feature generation)
    stage_w_async(We, EF, 0, Wbuf0, tid);
    cp_commit();

    if (tid < TOPK) {
        int k = tid;
        int j = g_eidx[i * TOPK + k];
        int offr = ridx[i] - ridx[j];
        int ec = (clab[i] == clab[j]) ? 1 : 0;
        int d = min(max(offr + 32, 0), 64) * ec + (1 - ec) * 65;
        float* fr = feats + k * EF;
        #pragma unroll
        for (int f = 0; f < 16; f++) fr[f] = Wpos[f * 66 + d] + bpos[f];
        rbf_gen<16>(g_dnb[i * TOPK + k], 1.0f, fr + 16, E_SINV, E_D2, E_E2);
    }

    const signed char pa[24] = {0,2,3,4,1,1,1,1,0,0,0,4,4,3,0,2,3,4,2,3,4,2,3,2};
    const signed char pb[24] = {0,2,3,4,0,2,3,4,2,3,4,2,3,2,1,1,1,1,0,0,0,4,4,3};
    for (int tt = tid; tt < TOPK * 24; tt += 256) {
        int k = tt / 24, p = tt - k * 24;
        int j = g_eidx[i * TOPK + k];
        const float* A = g_coords + i * 15 + (int)pa[p] * 3;
        const float* B = g_coords + j * 15 + (int)pb[p] * 3;
        float dx = A[0] - B[0], dy = A[1] - B[1], dz = A[2] - B[2];
        float D = sqrtf(dx * dx + dy * dy + dz * dz + 1e-6f);
        rbf_gen<16>(D, 1.0f, feats + k * EF + 32 + p * 16, E_SINV, E_D2, E_E2);
    }

    int eg = wid >> 1;
    int chh = wid & 1;
    int op = chh * 64 + 2 * lane;
    unsigned long long acc0[12], acc1[12];
    #pragma unroll
    for (int k = 0; k < 12; k++) { acc0[k] = 0ull; acc1[k] = 0ull; }

    const int NST = EF / 32;
    for (int st = 0; st < NST; st++) {
        cp_wait0();
        __syncthreads();
        if (st + 1 < NST) {
            unsigned long long* Wnxt = (st & 1) ? Wbuf0 : Wbuf1;
            stage_w_async(We, EF, (st + 1) * 32, Wnxt, tid);
            cp_commit();
        }
        unsigned long long* Wcur = (st & 1) ? Wbuf1 : Wbuf0;
        const float* fb = feats + st * 32;
        #pragma unroll
        for (int q = 0; q < 8; q++) {
            ulonglong2 wa = *(const ulonglong2*)(Wcur + (2 * q) * WP + op);
            ulonglong2 wb = *(const ulonglong2*)(Wcur + (2 * q + 1) * WP + op);
            #pragma unroll
            for (int k = 0; k < 12; k++) {
                ulonglong2 v = *(const ulonglong2*)(fb + (eg * 12 + k) * EF + 4 * q);
                acc0[k] = fma2(wa.x, v.x, acc0[k]);
                acc0[k] = fma2(wb.x, v.y, acc0[k]);
                acc1[k] = fma2(wa.y, v.x, acc1[k]);
                acc1[k] = fma2(wb.y, v.y, acc1[k]);
            }
        }
    }
    __syncthreads();

    float* h = feats;  // 48*128
    #pragma unroll
    for (int k = 0; k < 12; k++) {
        h[(eg * 12 + k) * 128 + op] = pairsum(acc0[k]);
        h[(eg * 12 + k) * 128 + op + 1] = pairsum(acc1[k]);
    }
    __syncthreads();

    for (int k = wid; k < TOPK; k += 8) {
        float v0 = h[k * 128 + lane];
        float v1 = h[k * 128 + lane + 32];
        float v2 = h[k * 128 + lane + 64];
        float v3 = h[k * 128 + lane + 96];
        float s = v0 + v1 + v2 + v3;
        for (int off = 16; off; off >>= 1) s += __shfl_xor_sync(0xffffffffu, s, off);
        float mu = s * (1.0f / 128.0f);
        float d0 = v0 - mu, d1 = v1 - mu, d2 = v2 - mu, d3 = v3 - mu;
        float s2 = d0 * d0 + d1 * d1 + d2 * d2 + d3 * d3;
        for (int off = 16; off; off >>= 1) s2 += __shfl_xor_sync(0xffffffffu, s2, off);
        float inv = rsqrtf(s2 * (1.0f / 128.0f) + 1e-5f);
        size_t base = OFF_E + ((size_t)(i * TOPK + k)) * 128;
        out[base + lane]      = ge[lane]      * d0 * inv + be[lane];
        out[base + lane + 32] = ge[lane + 32] * d1 * inv + be[lane + 32];
        out[base + lane + 64] = ge[lane + 64] * d2 * inv + be[lane + 64];
        out[base + lane + 96] = ge[lane + 96] * d3 * inv + be[lane + 96];
    }
}

// ---------------------------------------------------------------------------
// Kernel 4: E_s. 256 threads, warp = (edge-group[2] x 8, ch-half[2], feat-half[2]).
// cp.async double-buffered W staging, 1 barrier per stage.
// ---------------------------------------------------------------------------
__global__ void __launch_bounds__(256, 2) es_kernel(
    const float* __restrict__ X, const float* __restrict__ amask,
    const float* __restrict__ Ws, const float* __restrict__ gs,
    const float* __restrict__ bs, float* __restrict__ out) {
    extern __shared__ float feats[];  // 16*1280 floats, then 2x Wsm2[16*WP]
    unsigned long long* Wbuf0 = (unsigned long long*)(feats + KT * SF);
    unsigned long long* Wbuf1 = Wbuf0 + 16 * WP;
    __shared__ int jn[KT];
    __shared__ float anch[15];

    int bx = blockIdx.x;
    int i = bx / NTILE;
    int k0 = (bx - i * NTILE) * KT;
    int tid = threadIdx.x;
    int wid = tid >> 5, lane = tid & 31;

    stage_w_async(Ws, SF, 0, Wbuf0, tid);
    cp_commit();

    if (tid < KT) jn[tid] = g_eidx[i * TOPK + k0 + tid];
    if (tid >= 32 && tid < 47) anch[tid - 32] = g_coords[i * 15 + (tid - 32)];
    __syncthreads();

    for (int tt = tid; tt < KT * 160; tt += 256) {
        int kk = tt / 160;
        int rem = tt - kk * 160;
        int a = rem >> 5, s = rem & 31;
        int j = jn[kk];
        const float* Sp = X + ((size_t)j * 37 + 5 + s) * 3;
        float dx = anch[a * 3 + 0] - Sp[0];
        float dy = anch[a * 3 + 1] - Sp[1];
        float dz = anch[a * 3 + 2] - Sp[2];
        float D = sqrtf(dx * dx + dy * dy + dz * dz + 1e-6f);
        float m = amask[(size_t)j * 37 + 5 + s];
        rbf_gen<8>(D, m, feats + kk * SF + (a * 32 + s) * 8, S_SINV, S_D2, S_E2);
    }

    int eg = wid >> 2;         // 2 edge groups x 8 edges
    int chh = (wid >> 1) & 1;  // channel half
    int fh = wid & 1;          // feature half of each 32-feat stage
    int op = chh * 64 + 2 * lane;
    unsigned long long acc0[8], acc1[8];
    #pragma unroll
    for (int k = 0; k < 8; k++) { acc0[k] = 0ull; acc1[k] = 0ull; }

    const int NST = SF / 32;
    for (int st = 0; st < NST; st++) {
        cp_wait0();
        __syncthreads();
        if (st + 1 < NST) {
            unsigned long long* Wnxt = (st & 1) ? Wbuf0 : Wbuf1;
            stage_w_async(Ws, SF, (st + 1) * 32, Wnxt, tid);
            cp_commit();
        }
        unsigned long long* Wcur = (st & 1) ? Wbuf1 : Wbuf0;
        const float* fb = feats + st * 32 + fh * 16;
        #pragma unroll
        for (int q = 0; q < 4; q++) {
            int f2a = fh * 8 + 2 * q;
            ulonglong2 wa = *(const ulonglong2*)(Wcur + f2a * WP + op);
            ulonglong2 wb = *(const ulonglong2*)(Wcur + (f2a + 1) * WP + op);
            #pragma unroll
            for (int k = 0; k < 8; k++) {
                ulonglong2 v = *(const ulonglong2*)(fb + (eg * 8 + k) * SF + 4 * q);
                acc0[k] = fma2(wa.x, v.x, acc0[k]);
                acc0[k] = fma2(wb.x, v.y, acc0[k]);
                acc1[k] = fma2(wa.y, v.x, acc1[k]);
                acc1[k] = fma2(wb.y, v.y, acc1[k]);
            }
        }
    }
    __syncthreads();

    float* h = feats;  // 16*128
    if (fh == 0) {
        #pragma unroll
        for (int k = 0; k < 8; k++) {
            h[(eg * 8 + k) * 128 + op] = pairsum(acc0[k]);
            h[(eg * 8 + k) * 128 + op + 1] = pairsum(acc1[k]);
        }
    }
    __syncthreads();
    if (fh == 1) {
        #pragma unroll
        for (int k = 0; k < 8; k++) {
            h[(eg * 8 + k) * 128 + op] += pairsum(acc0[k]);
            h[(eg * 8 + k) * 128 + op + 1] += pairsum(acc1[k]);
        }
    }
    __syncthreads();

    for (int kk = wid; kk < KT; kk += 8) {
        float v0 = h[kk * 128 + lane];
        float v1 = h[kk * 128 + lane + 32];
        float v2 = h[kk * 128 + lane + 64];
        float v3 = h[kk * 128 + lane + 96];
        float s = v0 + v1 + v2 + v3;
        for (int off = 16; off; off >>= 1) s += __shfl_xor_sync(0xffffffffu, s, off);
        float mu = s * (1.0f / 128.0f);
        float d0 = v0 - mu, d1 = v1 - mu, d2 = v2 - mu, d3 = v3 - mu;
        float s2 = d0 * d0 + d1 * d1 + d2 * d2 + d3 * d3;
        for (int off = 16; off; off >>= 1) s2 += __shfl_xor_sync(0xffffffffu, s2, off);
        float inv = rsqrtf(s2 * (1.0f / 128.0f) + 1e-5f);
        size_t base = OFF_ES + ((size_t)(i * TOPK + k0 + kk)) * 128;
        out[base + lane]      = gs[lane]      * d0 * inv + bs[lane];
        out[base + lane + 32] = gs[lane + 32] * d1 * inv + bs[lane + 32];
        out[base + lane + 64] = gs[lane + 64] * d2 * inv + bs[lane + 64];
        out[base + lane + 96] = gs[lane + 96] * d3 * inv + bs[lane + 96];
    }
}

// ---------------------------------------------------------------------------
extern "C" void kernel_launch(void* const* d_in, const int* in_sizes, int n_in,
                              void* d_out, int out_size) {
    (void)in_sizes; (void)n_in; (void)out_size;
    const float* X     = (const float*)d_in[0];
    const float* mask  = (const float*)d_in[2];
    const float* amask = (const float*)d_in[3];
    const int*   ridx  = (const int*)d_in[4];
    const int*   clab  = (const int*)d_in[6];
    const float* Wpos  = (const float*)d_in[7];
    const float* bpos  = (const float*)d_in[8];
    const float* We    = (const float*)d_in[9];
    const float* ge    = (const float*)d_in[10];
    const float* be    = (const float*)d_in[11];
    const float* Ws    = (const float*)d_in[12];
    const float* gs    = (const float*)d_in[13];
    const float* bs    = (const float*)d_in[14];
    float* out = (float*)d_out;

    int e_smem  = TOPK * EF * 4 + 2 * 16 * WP * 8;   // 79872 + 33280 = 113152
    int es_smem = KT * SF * 4 + 2 * 16 * WP * 8;     // 81920 + 33280 = 115200
    cudaFuncSetAttribute(e_kernel, cudaFuncAttributeMaxDynamicSharedMemorySize,
                         e_smem);
    cudaFuncSetAttribute(es_kernel, cudaFuncAttributeMaxDynamicSharedMemorySize,
                         es_smem);

    geom_kernel<<<(LRES + 255) / 256, 256>>>(X);
    topk_kernel<<<LRES, 256>>>(X, mask, out);
    e_kernel<<<LRES, 256, e_smem>>>(Wpos, bpos, ridx, clab, We, ge, be, out);
    es_kernel<<<LRES * NTILE, 256, es_smem>>>(X, amask, Ws, gs, bs, out);
}

// round 10
// speedup vs baseline: 2.2784x; 2.1320x over previous
#include <cuda_runtime.h>

#define LRES 1024
#define TOPK 48
#define EF   416
#define SF   1280
#define WP   130   // e_kernel Wsm2 pitch in ull

#define OFF_E       0ull
#define OFF_EIDX    6291456ull
#define OFF_ES      6340608ull
#define OFF_EIDXSUB 12632064ull

__device__ float g_coords[LRES * 15];
__device__ int   g_eidx[LRES * TOPK];
__device__ float g_dnb[LRES * TOPK];
__device__ float g_wsr[128 * SF];   // tf32-rounded W_s

__device__ __forceinline__ unsigned long long u64min_(unsigned long long a,
                                                      unsigned long long b) {
    return a < b ? a : b;
}

__device__ __forceinline__ unsigned long long fma2(unsigned long long a,
                                                   unsigned long long b,
                                                   unsigned long long c) {
    unsigned long long d;
    asm("fma.rn.f32x2 %0, %1, %2, %3;" : "=l"(d) : "l"(a), "l"(b), "l"(c));
    return d;
}

__device__ __forceinline__ float pairsum(unsigned long long v) {
    float lo, hi;
    asm("mov.b64 {%0, %1}, %2;" : "=f"(lo), "=f"(hi) : "l"(v));
    return lo + hi;
}

__device__ __forceinline__ void cp_commit() {
    asm volatile("cp.async.commit_group;" ::: "memory");
}
__device__ __forceinline__ void cp_wait0() {
    asm volatile("cp.async.wait_group 0;" ::: "memory");
}

__device__ __forceinline__ unsigned cvt_tf32(float x) {
    unsigned u;
    asm("cvt.rna.tf32.f32 %0, %1;" : "=r"(u) : "f"(x));
    return u;
}

__device__ __forceinline__ void mma_tf32(float& d0, float& d1, float& d2,
                                         float& d3, unsigned a0, unsigned a1,
                                         unsigned a2, unsigned a3, unsigned b0,
                                         unsigned b1) {
    asm volatile(
        "mma.sync.aligned.m16n8k8.row.col.f32.tf32.tf32.f32 "
        "{%0,%1,%2,%3}, {%4,%5,%6,%7}, {%8,%9}, {%0,%1,%2,%3};"
        : "+f"(d0), "+f"(d1), "+f"(d2), "+f"(d3)
        : "r"(a0), "r"(a1), "r"(a2), "r"(a3), "r"(b0), "r"(b1));
}

// Chained RBF (2 expf instead of NB), guarded reverse chain vs underflow.
template <int NB>
__device__ __forceinline__ void rbf_gen(float D, float m, float* __restrict__ fr,
                                        float SINV, float D2, float E2c) {
    float s = (D - 2.0f) * SINV;
    float v = __expf(-D2 * s * s);
    float g = __expf(D2 * (2.0f * s - 1.0f));
    float vals[NB];
    vals[0] = v;
    #pragma unroll
    for (int r = 1; r < NB; r++) { v *= g; g *= E2c; vals[r] = v; }
    if (vals[0] < 1e-30f) {
        float sN = s - (float)(NB - 1);
        float v1 = __expf(-D2 * sN * sN);
        float g1 = __expf(-D2 * (2.0f * sN + 1.0f));
        vals[NB - 1] = fmaxf(vals[NB - 1], v1);
        #pragma unroll
        for (int r = NB - 2; r >= 0; r--) {
            v1 *= g1; g1 *= E2c;
            vals[r] = fmaxf(vals[r], v1);
        }
    }
    #pragma unroll
    for (int r = 0; r < NB; r++) fr[r] = m * vals[r];
}

#define E_SINV 0.75f
#define E_D2   1.13777778f
#define E_E2   0.10273980f
#define S_SINV 0.35f
#define S_D2   1.30612245f
#define S_E2   0.07336966f

// e_kernel staging (unchanged from R9)
__device__ __forceinline__ void stage_w_async(const float* __restrict__ W,
                                              int stride, int f0,
                                              unsigned long long* Wsm2,
                                              int tid) {
    #pragma unroll
    for (int p = tid; p < 2048; p += 256) {
        int o = p >> 4, f2 = p & 15;
        const float* src = W + (size_t)o * stride + f0 + 2 * f2;
        unsigned int dst =
            (unsigned int)__cvta_generic_to_shared(Wsm2 + f2 * WP + o);
        asm volatile("cp.async.ca.shared.global [%0], [%1], 8;"
                     :: "r"(dst), "l"(src) : "memory");
    }
}

// es staging: 128ch x 32feat fp32 tile -> Wsm[ch*36 + f], 16B cp.async
__device__ __forceinline__ void stage_ws_async(const float* __restrict__ Wsrc,
                                               int st, float* __restrict__ Wsm,
                                               int tid) {
    #pragma unroll
    for (int p = tid; p < 1024; p += 256) {
        int ch = p >> 3, fc = p & 7;
        const float* src = Wsrc + ch * SF + st * 32 + fc * 4;
        unsigned int dst =
            (unsigned int)__cvta_generic_to_shared(Wsm + ch * 36 + fc * 4);
        asm volatile("cp.async.ca.shared.global [%0], [%1], 16;"
                     :: "r"(dst), "l"(src) : "memory");
    }
}

// ---------------------------------------------------------------------------
__global__ void wcvt_kernel(const float* __restrict__ Ws) {
    int i = blockIdx.x * 256 + threadIdx.x;
    if (i < 128 * SF) g_wsr[i] = __uint_as_float(cvt_tf32(Ws[i]));
}

// ---------------------------------------------------------------------------
__global__ void geom_kernel(const float* __restrict__ X) {
    int i = blockIdx.x * blockDim.x + threadIdx.x;
    if (i >= LRES) return;
    const float* xi = X + (size_t)i * 37 * 3;
    float n0 = xi[0],  n1 = xi[1],  n2 = xi[2];
    float a0 = xi[3],  a1 = xi[4],  a2 = xi[5];
    float c0 = xi[6],  c1 = xi[7],  c2 = xi[8];
    float o0 = xi[12], o1 = xi[13], o2 = xi[14];
    float b0 = a0 - n0, b1 = a1 - n1, b2 = a2 - n2;
    float d0 = c0 - a0, d1 = c1 - a1, d2 = c2 - a2;
    float x0 = b1 * d2 - b2 * d1;
    float x1 = b2 * d0 - b0 * d2;
    float x2 = b0 * d1 - b1 * d0;
    float cb0 = -0.58273431f * x0 + 0.56802827f * b0 - 0.54067466f * d0 + a0;
    float cb1 = -0.58273431f * x1 + 0.56802827f * b1 - 0.54067466f * d1 + a1;
    float cb2 = -0.58273431f * x2 + 0.56802827f * b2 - 0.54067466f * d2 + a2;
    float* dst = g_coords + i * 15;
    dst[0] = n0;  dst[1] = n1;  dst[2] = n2;
    dst[3] = a0;  dst[4] = a1;  dst[5] = a2;
    dst[6] = c0;  dst[7] = c1;  dst[8] = c2;
    dst[9] = o0;  dst[10] = o1; dst[11] = o2;
    dst[12] = cb0; dst[13] = cb1; dst[14] = cb2;
}

// ---------------------------------------------------------------------------
__global__ void topk_kernel(const float* __restrict__ X,
                            const float* __restrict__ mask,
                            float* __restrict__ out) {
    __shared__ float dsh[LRES];
    __shared__ unsigned long long keys[LRES];
    __shared__ float wmaxs[8];
    __shared__ unsigned long long wmins[8];
    __shared__ float smDmax;

    int i = blockIdx.x;
    int tid = threadIdx.x;
    float cax = X[((size_t)i * 37 + 1) * 3 + 0];
    float cay = X[((size_t)i * 37 + 1) * 3 + 1];
    float caz = X[((size_t)i * 37 + 1) * 3 + 2];
    float mi = mask[i];

    float lmax = 0.0f;
    for (int j = tid; j < LRES; j += 256) {
        float dx = cax - X[((size_t)j * 37 + 1) * 3 + 0];
        float dy = cay - X[((size_t)j * 37 + 1) * 3 + 1];
        float dz = caz - X[((size_t)j * 37 + 1) * 3 + 2];
        float s = dx * dx + dy * dy + dz * dz;
        float m2 = mi * mask[j];
        float Dv = m2 * sqrtf(s + 1e-6f);
        dsh[j] = Dv;
        lmax = fmaxf(lmax, Dv);
    }
    for (int off = 16; off; off >>= 1)
        lmax = fmaxf(lmax, __shfl_xor_sync(0xffffffffu, lmax, off));
    if ((tid & 31) == 0) wmaxs[tid >> 5] = lmax;
    __syncthreads();
    if (tid == 0) {
        float m = wmaxs[0];
        #pragma unroll
        for (int w = 1; w < 8; w++) m = fmaxf(m, wmaxs[w]);
        smDmax = m;
    }
    __syncthreads();
    float Dmax = smDmax;

    for (int j = tid; j < LRES; j += 256) {
        float m2 = mi * mask[j];
        float Dadj = dsh[j] + (1.0f - m2) * Dmax;
        keys[j] = (((unsigned long long)__float_as_uint(Dadj)) << 32) |
                  (unsigned int)j;
    }
    __syncthreads();

    for (int sel = 0; sel < TOPK; sel++) {
        unsigned long long lmin = 0xffffffffffffffffull;
        #pragma unroll
        for (int c = 0; c < 4; c++) lmin = u64min_(lmin, keys[tid + 256 * c]);
        for (int off = 16; off; off >>= 1) {
            unsigned long long o2 = __shfl_xor_sync(0xffffffffu, lmin, off);
            lmin = u64min_(lmin, o2);
        }
        if ((tid & 31) == 0) wmins[tid >> 5] = lmin;
        __syncthreads();
        if (tid == 0) {
            unsigned long long m = wmins[0];
            #pragma unroll
            for (int w = 1; w < 8; w++) m = u64min_(m, wmins[w]);
            int j = (int)(m & 0xffffffffull);
            float dv = __uint_as_float((unsigned int)(m >> 32));
            g_eidx[i * TOPK + sel] = j;
            g_dnb[i * TOPK + sel] = dv;
            out[OFF_EIDX + (size_t)i * TOPK + sel] = (float)j;
            out[OFF_EIDXSUB + (size_t)i * TOPK + sel] = (float)j;
            keys[j] = 0xffffffffffffffffull;
        }
        __syncthreads();
    }
}

// ---------------------------------------------------------------------------
// Kernel 3: E (unchanged from R9, cp.async + fma2).
// ---------------------------------------------------------------------------
__global__ void __launch_bounds__(256, 2) e_kernel(
    const float* __restrict__ Wpos, const float* __restrict__ bpos,
    const int* __restrict__ ridx, const int* __restrict__ clab,
    const float* __restrict__ We, const float* __restrict__ ge,
    const float* __restrict__ be, float* __restrict__ out) {
    extern __shared__ float feats[];
    unsigned long long* Wbuf0 = (unsigned long long*)(feats + TOPK * EF);
    unsigned long long* Wbuf1 = Wbuf0 + 16 * WP;
    int i = blockIdx.x;
    int tid = threadIdx.x;
    int wid = tid >> 5, lane = tid & 31;

    stage_w_async(We, EF, 0, Wbuf0, tid);
    cp_commit();

    if (tid < TOPK) {
        int k = tid;
        int j = g_eidx[i * TOPK + k];
        int offr = ridx[i] - ridx[j];
        int ec = (clab[i] == clab[j]) ? 1 : 0;
        int d = min(max(offr + 32, 0), 64) * ec + (1 - ec) * 65;
        float* fr = feats + k * EF;
        #pragma unroll
        for (int f = 0; f < 16; f++) fr[f] = Wpos[f * 66 + d] + bpos[f];
        rbf_gen<16>(g_dnb[i * TOPK + k], 1.0f, fr + 16, E_SINV, E_D2, E_E2);
    }

    const signed char pa[24] = {0,2,3,4,1,1,1,1,0,0,0,4,4,3,0,2,3,4,2,3,4,2,3,2};
    const signed char pb[24] = {0,2,3,4,0,2,3,4,2,3,4,2,3,2,1,1,1,1,0,0,0,4,4,3};
    for (int tt = tid; tt < TOPK * 24; tt += 256) {
        int k = tt / 24, p = tt - k * 24;
        int j = g_eidx[i * TOPK + k];
        const float* A = g_coords + i * 15 + (int)pa[p] * 3;
        const float* B = g_coords + j * 15 + (int)pb[p] * 3;
        float dx = A[0] - B[0], dy = A[1] - B[1], dz = A[2] - B[2];
        float D = sqrtf(dx * dx + dy * dy + dz * dz + 1e-6f);
        rbf_gen<16>(D, 1.0f, feats + k * EF + 32 + p * 16, E_SINV, E_D2, E_E2);
    }

    int eg = wid >> 1;
    int chh = wid & 1;
    int op = chh * 64 + 2 * lane;
    unsigned long long acc0[12], acc1[12];
    #pragma unroll
    for (int k = 0; k < 12; k++) { acc0[k] = 0ull; acc1[k] = 0ull; }

    const int NST = EF / 32;
    for (int st = 0; st < NST; st++) {
        cp_wait0();
        __syncthreads();
        if (st + 1 < NST) {
            unsigned long long* Wnxt = (st & 1) ? Wbuf0 : Wbuf1;
            stage_w_async(We, EF, (st + 1) * 32, Wnxt, tid);
            cp_commit();
        }
        unsigned long long* Wcur = (st & 1) ? Wbuf1 : Wbuf0;
        const float* fb = feats + st * 32;
        #pragma unroll
        for (int q = 0; q < 8; q++) {
            ulonglong2 wa = *(const ulonglong2*)(Wcur + (2 * q) * WP + op);
            ulonglong2 wb = *(const ulonglong2*)(Wcur + (2 * q + 1) * WP + op);
            #pragma unroll
            for (int k = 0; k < 12; k++) {
                ulonglong2 v = *(const ulonglong2*)(fb + (eg * 12 + k) * EF + 4 * q);
                acc0[k] = fma2(wa.x, v.x, acc0[k]);
                acc0[k] = fma2(wb.x, v.y, acc0[k]);
                acc1[k] = fma2(wa.y, v.x, acc1[k]);
                acc1[k] = fma2(wb.y, v.y, acc1[k]);
            }
        }
    }
    __syncthreads();

    float* h = feats;
    #pragma unroll
    for (int k = 0; k < 12; k++) {
        h[(eg * 12 + k) * 128 + op] = pairsum(acc0[k]);
        h[(eg * 12 + k) * 128 + op + 1] = pairsum(acc1[k]);
    }
    __syncthreads();

    for (int k = wid; k < TOPK; k += 8) {
        float v0 = h[k * 128 + lane];
        float v1 = h[k * 128 + lane + 32];
        float v2 = h[k * 128 + lane + 64];
        float v3 = h[k * 128 + lane + 96];
        float s = v0 + v1 + v2 + v3;
        for (int off = 16; off; off >>= 1) s += __shfl_xor_sync(0xffffffffu, s, off);
        float mu = s * (1.0f / 128.0f);
        float d0 = v0 - mu, d1 = v1 - mu, d2 = v2 - mu, d3 = v3 - mu;
        float s2 = d0 * d0 + d1 * d1 + d2 * d2 + d3 * d3;
        for (int off = 16; off; off >>= 1) s2 += __shfl_xor_sync(0xffffffffu, s2, off);
        float inv = rsqrtf(s2 * (1.0f / 128.0f) + 1e-5f);
        size_t base = OFF_E + ((size_t)(i * TOPK + k)) * 128;
        out[base + lane]      = ge[lane]      * d0 * inv + be[lane];
        out[base + lane + 32] = ge[lane + 32] * d1 * inv + be[lane + 32];
        out[base + lane + 64] = ge[lane + 64] * d2 * inv + be[lane + 64];
        out[base + lane + 96] = ge[lane + 96] * d3 * inv + be[lane + 96];
    }
}

// ---------------------------------------------------------------------------
// Kernel 4: E_s via tf32 mma.sync. One block per residue: M=48 (3 m16 tiles),
// N=128 (8 warps x 16 ch), K=1280 (40 stages of 32 feats, fused RBF gen).
// smem (floats): W0[4608] W1[4608] A[1728] SDv[7840] SDg[7840]; h aliases SDv.
// ---------------------------------------------------------------------------
#define ES_W0  0
#define ES_W1  4608
#define ES_A   9216
#define ES_SDV 10944
#define ES_SDG 18784
#define ES_TOT 26624

__global__ void __launch_bounds__(256, 2) es_kernel(
    const float* __restrict__ X, const float* __restrict__ amask,
    const float* __restrict__ gs, const float* __restrict__ bs,
    float* __restrict__ out) {
    extern __shared__ float sm[];
    float* Asm = sm + ES_A;
    float* SDv = sm + ES_SDV;
    float* SDg = sm + ES_SDG;
    __shared__ int jn[TOPK];
    __shared__ float anch[15];

    int i = blockIdx.x;
    int tid = threadIdx.x;
    int wid = tid >> 5, lane = tid & 31;
    int g = lane >> 2, t = lane & 3;

    stage_ws_async(g_wsr, 0, sm + ES_W0, tid);
    cp_commit();

    if (tid < TOPK) jn[tid] = g_eidx[i * TOPK + tid];
    if (tid >= 64 && tid < 79) anch[tid - 64] = g_coords[i * 15 + (tid - 64)];
    __syncthreads();

    // Seed phase: per (edge, sidechain atom) load coords once, write 5 anchors'
    // RBF seeds (v0*m, g) into SDv/SDg[cell*49 + e].
    #pragma unroll
    for (int it = 0; it < 6; it++) {
        int task = tid + 256 * it;      // 48*32 = 1536 tasks
        int e = task >> 5, s = task & 31;
        int j = jn[e];
        size_t bi = (size_t)j * 37 + 5 + s;
        float x0 = X[bi * 3 + 0], x1 = X[bi * 3 + 1], x2 = X[bi * 3 + 2];
        float m = amask[bi];
        #pragma unroll
        for (int a = 0; a < 5; a++) {
            float dx = anch[a * 3 + 0] - x0;
            float dy = anch[a * 3 + 1] - x1;
            float dz = anch[a * 3 + 2] - x2;
            float D = sqrtf(dx * dx + dy * dy + dz * dz + 1e-6f);
            float sc = (D - 2.0f) * S_SINV;
            float v = m * __expf(-S_D2 * sc * sc);
            float gg = __expf(S_D2 * (2.0f * sc - 1.0f));
            int cell = a * 32 + s;
            SDv[cell * 49 + e] = v;
            SDg[cell * 49 + e] = gg;
        }
    }
    __syncthreads();

    // Expansion for stage 0
    if (tid < 192) {
        int e = tid >> 2, c4 = tid & 3;
        float v = SDv[c4 * 49 + e];
        float gg = SDg[c4 * 49 + e];
        float vals[8];
        vals[0] = v;
        #pragma unroll
        for (int r = 1; r < 8; r++) { v *= gg; gg *= S_E2; vals[r] = v; }
        float4 f0, f1;
        f0.x = __uint_as_float(cvt_tf32(vals[0]));
        f0.y = __uint_as_float(cvt_tf32(vals[1]));
        f0.z = __uint_as_float(cvt_tf32(vals[2]));
        f0.w = __uint_as_float(cvt_tf32(vals[3]));
        f1.x = __uint_as_float(cvt_tf32(vals[4]));
        f1.y = __uint_as_float(cvt_tf32(vals[5]));
        f1.z = __uint_as_float(cvt_tf32(vals[6]));
        f1.w = __uint_as_float(cvt_tf32(vals[7]));
        *(float4*)(Asm + e * 36 + c4 * 8) = f0;
        *(float4*)(Asm + e * 36 + c4 * 8 + 4) = f1;
    }

    int n0 = wid * 16;
    float acc[3][2][4];
    #pragma unroll
    for (int mt = 0; mt < 3; mt++)
        #pragma unroll
        for (int j = 0; j < 2; j++)
            #pragma unroll
            for (int q = 0; q < 4; q++) acc[mt][j][q] = 0.0f;

    for (int st = 0; st < 40; st++) {
        cp_wait0();
        __syncthreads();   // W[st] landed, A[st] written
        if (st + 1 < 40) {
            stage_ws_async(g_wsr, st + 1, sm + ((st & 1) ? ES_W0 : ES_W1), tid);
            cp_commit();
        }
        const float* Wc = sm + ((st & 1) ? ES_W1 : ES_W0);
        #pragma unroll
        for (int k8 = 0; k8 < 4; k8++) {
            int ko = k8 * 8;
            unsigned af[3][4];
            #pragma unroll
            for (int mt = 0; mt < 3; mt++) {
                const float* Ab = Asm + (mt * 16) * 36;
                af[mt][0] = __float_as_uint(Ab[g * 36 + ko + t]);
                af[mt][1] = __float_as_uint(Ab[(g + 8) * 36 + ko + t]);
                af[mt][2] = __float_as_uint(Ab[g * 36 + ko + t + 4]);
                af[mt][3] = __float_as_uint(Ab[(g + 8) * 36 + ko + t + 4]);
            }
            #pragma unroll
            for (int j = 0; j < 2; j++) {
                unsigned b0 = __float_as_uint(Wc[(n0 + 8 * j + g) * 36 + ko + t]);
                unsigned b1 = __float_as_uint(Wc[(n0 + 8 * j + g) * 36 + ko + t + 4]);
                #pragma unroll
                for (int mt = 0; mt < 3; mt++)
                    mma_tf32(acc[mt][j][0], acc[mt][j][1], acc[mt][j][2],
                             acc[mt][j][3], af[mt][0], af[mt][1], af[mt][2],
                             af[mt][3], b0, b1);
            }
        }
        __syncthreads();   // mma reads of A done
        if (st + 1 < 40 && tid < 192) {
            int e = tid >> 2, c4 = tid & 3;
            int cell = 4 * (st + 1) + c4;
            float v = SDv[cell * 49 + e];
            float gg = SDg[cell * 49 + e];
            float vals[8];
            vals[0] = v;
            #pragma unroll
            for (int r = 1; r < 8; r++) { v *= gg; gg *= S_E2; vals[r] = v; }
            float4 f0, f1;
            f0.x = __uint_as_float(cvt_tf32(vals[0]));
            f0.y = __uint_as_float(cvt_tf32(vals[1]));
            f0.z = __uint_as_float(cvt_tf32(vals[2]));
            f0.w = __uint_as_float(cvt_tf32(vals[3]));
            f1.x = __uint_as_float(cvt_tf32(vals[4]));
            f1.y = __uint_as_float(cvt_tf32(vals[5]));
            f1.z = __uint_as_float(cvt_tf32(vals[6]));
            f1.w = __uint_as_float(cvt_tf32(vals[7]));
            *(float4*)(Asm + e * 36 + c4 * 8) = f0;
            *(float4*)(Asm + e * 36 + c4 * 8 + 4) = f1;
        }
    }
    __syncthreads();

    // write accumulators to h (aliases SDv region)
    float* h = SDv;
    #pragma unroll
    for (int mt = 0; mt < 3; mt++)
        #pragma unroll
        for (int j = 0; j < 2; j++) {
            int col = n0 + 8 * j + 2 * t;
            *(float2*)(h + (mt * 16 + g) * 128 + col) =
                make_float2(acc[mt][j][0], acc[mt][j][1]);
            *(float2*)(h + (mt * 16 + g + 8) * 128 + col) =
                make_float2(acc[mt][j][2], acc[mt][j][3]);
        }
    __syncthreads();

    for (int kk = wid; kk < TOPK; kk += 8) {
        float v0 = h[kk * 128 + lane];
        float v1 = h[kk * 128 + lane + 32];
        float v2 = h[kk * 128 + lane + 64];
        float v3 = h[kk * 128 + lane + 96];
        float s = v0 + v1 + v2 + v3;
        for (int off = 16; off; off >>= 1) s += __shfl_xor_sync(0xffffffffu, s, off);
        float mu = s * (1.0f / 128.0f);
        float d0 = v0 - mu, d1 = v1 - mu, d2 = v2 - mu, d3 = v3 - mu;
        float s2 = d0 * d0 + d1 * d1 + d2 * d2 + d3 * d3;
        for (int off = 16; off; off >>= 1) s2 += __shfl_xor_sync(0xffffffffu, s2, off);
        float inv = rsqrtf(s2 * (1.0f / 128.0f) + 1e-5f);
        size_t base = OFF_ES + ((size_t)(i * TOPK + kk)) * 128;
        out[base + lane]      = gs[lane]      * d0 * inv + bs[lane];
        out[base + lane + 32] = gs[lane + 32] * d1 * inv + bs[lane + 32];
        out[base + lane + 64] = gs[lane + 64] * d2 * inv + bs[lane + 64];
        out[base + lane + 96] = gs[lane + 96] * d3 * inv + bs[lane + 96];
    }
}

// ---------------------------------------------------------------------------
extern "C" void kernel_launch(void* const* d_in, const int* in_sizes, int n_in,
                              void* d_out, int out_size) {
    (void)in_sizes; (void)n_in; (void)out_size;
    const float* X     = (const float*)d_in[0];
    const float* mask  = (const float*)d_in[2];
    const float* amask = (const float*)d_in[3];
    const int*   ridx  = (const int*)d_in[4];
    const int*   clab  = (const int*)d_in[6];
    const float* Wpos  = (const float*)d_in[7];
    const float* bpos  = (const float*)d_in[8];
    const float* We    = (const float*)d_in[9];
    const float* ge    = (const float*)d_in[10];
    const float* be    = (const float*)d_in[11];
    const float* Ws    = (const float*)d_in[12];
    const float* gs    = (const float*)d_in[13];
    const float* bs    = (const float*)d_in[14];
    float* out = (float*)d_out;

    int e_smem  = TOPK * EF * 4 + 2 * 16 * WP * 8;   // 113152
    int es_smem = ES_TOT * 4;                        // 106496
    cudaFuncSetAttribute(e_kernel, cudaFuncAttributeMaxDynamicSharedMemorySize,
                         e_smem);
    cudaFuncSetAttribute(es_kernel, cudaFuncAttributeMaxDynamicSharedMemorySize,
                         es_smem);

    geom_kernel<<<(LRES + 255) / 256, 256>>>(X);
    wcvt_kernel<<<(128 * SF + 255) / 256, 256>>>(Ws);
    topk_kernel<<<LRES, 256>>>(X, mask, out);
    e_kernel<<<LRES, 256, e_smem>>>(Wpos, bpos, ridx, clab, We, ge, be, out);
    es_kernel<<<LRES, 256, es_smem>>>(X, amask, gs, bs, out);
}

// round 11
// speedup vs baseline: 2.7386x; 1.2020x over previous
#include <cuda_runtime.h>

#define LRES 1024
#define TOPK 48
#define EF   416
#define SF   1280

#define OFF_E       0ull
#define OFF_EIDX    6291456ull
#define OFF_ES      6340608ull
#define OFF_EIDXSUB 12632064ull

__device__ float g_coords[LRES * 15];
__device__ int   g_eidx[LRES * TOPK];
__device__ float g_dnb[LRES * TOPK];
__device__ float g_wsr[128 * SF];   // tf32-rounded W_s
__device__ float g_wer[128 * EF];   // tf32-rounded W_e

__device__ __forceinline__ unsigned long long u64min_(unsigned long long a,
                                                      unsigned long long b) {
    return a < b ? a : b;
}

__device__ __forceinline__ void cp_commit() {
    asm volatile("cp.async.commit_group;" ::: "memory");
}
__device__ __forceinline__ void cp_wait0() {
    asm volatile("cp.async.wait_group 0;" ::: "memory");
}

__device__ __forceinline__ unsigned cvt_tf32(float x) {
    unsigned u;
    asm("cvt.rna.tf32.f32 %0, %1;" : "=r"(u) : "f"(x));
    return u;
}
__device__ __forceinline__ float tf32f(float x) {
    return __uint_as_float(cvt_tf32(x));
}

__device__ __forceinline__ void mma_tf32(float& d0, float& d1, float& d2,
                                         float& d3, unsigned a0, unsigned a1,
                                         unsigned a2, unsigned a3, unsigned b0,
                                         unsigned b1) {
    asm volatile(
        "mma.sync.aligned.m16n8k8.row.col.f32.tf32.tf32.f32 "
        "{%0,%1,%2,%3}, {%4,%5,%6,%7}, {%8,%9}, {%0,%1,%2,%3};"
        : "+f"(d0), "+f"(d1), "+f"(d2), "+f"(d3)
        : "r"(a0), "r"(a1), "r"(a2), "r"(a3), "r"(b0), "r"(b1));
}

// Chained RBF; ROUND -> store tf32-rounded values.
template <int NB, bool ROUND>
__device__ __forceinline__ void rbf_gen(float D, float m, float* __restrict__ fr,
                                        float SINV, float D2, float E2c) {
    float s = (D - 2.0f) * SINV;
    float v = __expf(-D2 * s * s);
    float g = __expf(D2 * (2.0f * s - 1.0f));
    float vals[NB];
    vals[0] = v;
    #pragma unroll
    for (int r = 1; r < NB; r++) { v *= g; g *= E2c; vals[r] = v; }
    if (vals[0] < 1e-30f) {
        float sN = s - (float)(NB - 1);
        float v1 = __expf(-D2 * sN * sN);
        float g1 = __expf(-D2 * (2.0f * sN + 1.0f));
        vals[NB - 1] = fmaxf(vals[NB - 1], v1);
        #pragma unroll
        for (int r = NB - 2; r >= 0; r--) {
            v1 *= g1; g1 *= E2c;
            vals[r] = fmaxf(vals[r], v1);
        }
    }
    #pragma unroll
    for (int r = 0; r < NB; r++)
        fr[r] = ROUND ? tf32f(m * vals[r]) : m * vals[r];
}

#define E_SINV 0.75f
#define E_D2   1.13777778f
#define E_E2   0.10273980f
#define S_SINV 0.35f
#define S_D2   1.30612245f
#define S_E2   0.07336966f

// stage 128ch x 32feat fp32 tile -> Wsm[ch*36 + f], 16B cp.async
__device__ __forceinline__ void stage_ws_async(const float* __restrict__ Wsrc,
                                               int stride, int st,
                                               float* __restrict__ Wsm,
                                               int tid) {
    #pragma unroll
    for (int p = tid; p < 1024; p += 256) {
        int ch = p >> 3, fc = p & 7;
        const float* src = Wsrc + ch * stride + st * 32 + fc * 4;
        unsigned int dst =
            (unsigned int)__cvta_generic_to_shared(Wsm + ch * 36 + fc * 4);
        asm volatile("cp.async.ca.shared.global [%0], [%1], 16;"
                     :: "r"(dst), "l"(src) : "memory");
    }
}

// ---------------------------------------------------------------------------
__global__ void wcvt_kernel(const float* __restrict__ Ws,
                            const float* __restrict__ We) {
    int i = blockIdx.x * 256 + threadIdx.x;
    if (i < 128 * SF) g_wsr[i] = tf32f(Ws[i]);
    if (i < 128 * EF) g_wer[i] = tf32f(We[i]);
}

// ---------------------------------------------------------------------------
__global__ void geom_kernel(const float* __restrict__ X) {
    int i = blockIdx.x * blockDim.x + threadIdx.x;
    if (i >= LRES) return;
    const float* xi = X + (size_t)i * 37 * 3;
    float n0 = xi[0],  n1 = xi[1],  n2 = xi[2];
    float a0 = xi[3],  a1 = xi[4],  a2 = xi[5];
    float c0 = xi[6],  c1 = xi[7],  c2 = xi[8];
    float o0 = xi[12], o1 = xi[13], o2 = xi[14];
    float b0 = a0 - n0, b1 = a1 - n1, b2 = a2 - n2;
    float d0 = c0 - a0, d1 = c1 - a1, d2 = c2 - a2;
    float x0 = b1 * d2 - b2 * d1;
    float x1 = b2 * d0 - b0 * d2;
    float x2 = b0 * d1 - b1 * d0;
    float cb0 = -0.58273431f * x0 + 0.56802827f * b0 - 0.54067466f * d0 + a0;
    float cb1 = -0.58273431f * x1 + 0.56802827f * b1 - 0.54067466f * d1 + a1;
    float cb2 = -0.58273431f * x2 + 0.56802827f * b2 - 0.54067466f * d2 + a2;
    float* dst = g_coords + i * 15;
    dst[0] = n0;  dst[1] = n1;  dst[2] = n2;
    dst[3] = a0;  dst[4] = a1;  dst[5] = a2;
    dst[6] = c0;  dst[7] = c1;  dst[8] = c2;
    dst[9] = o0;  dst[10] = o1; dst[11] = o2;
    dst[12] = cb0; dst[13] = cb1; dst[14] = cb2;
}

// ---------------------------------------------------------------------------
__global__ void topk_kernel(const float* __restrict__ X,
                            const float* __restrict__ mask,
                            float* __restrict__ out) {
    __shared__ float dsh[LRES];
    __shared__ unsigned long long keys[LRES];
    __shared__ float wmaxs[8];
    __shared__ unsigned long long wmins[8];
    __shared__ float smDmax;

    int i = blockIdx.x;
    int tid = threadIdx.x;
    float cax = X[((size_t)i * 37 + 1) * 3 + 0];
    float cay = X[((size_t)i * 37 + 1) * 3 + 1];
    float caz = X[((size_t)i * 37 + 1) * 3 + 2];
    float mi = mask[i];

    float lmax = 0.0f;
    for (int j = tid; j < LRES; j += 256) {
        float dx = cax - X[((size_t)j * 37 + 1) * 3 + 0];
        float dy = cay - X[((size_t)j * 37 + 1) * 3 + 1];
        float dz = caz - X[((size_t)j * 37 + 1) * 3 + 2];
        float s = dx * dx + dy * dy + dz * dz;
        float m2 = mi * mask[j];
        float Dv = m2 * sqrtf(s + 1e-6f);
        dsh[j] = Dv;
        lmax = fmaxf(lmax, Dv);
    }
    for (int off = 16; off; off >>= 1)
        lmax = fmaxf(lmax, __shfl_xor_sync(0xffffffffu, lmax, off));
    if ((tid & 31) == 0) wmaxs[tid >> 5] = lmax;
    __syncthreads();
    if (tid == 0) {
        float m = wmaxs[0];
        #pragma unroll
        for (int w = 1; w < 8; w++) m = fmaxf(m, wmaxs[w]);
        smDmax = m;
    }
    __syncthreads();
    float Dmax = smDmax;

    for (int j = tid; j < LRES; j += 256) {
        float m2 = mi * mask[j];
        float Dadj = dsh[j] + (1.0f - m2) * Dmax;
        keys[j] = (((unsigned long long)__float_as_uint(Dadj)) << 32) |
                  (unsigned int)j;
    }
    __syncthreads();

    for (int sel = 0; sel < TOPK; sel++) {
        unsigned long long lmin = 0xffffffffffffffffull;
        #pragma unroll
        for (int c = 0; c < 4; c++) lmin = u64min_(lmin, keys[tid + 256 * c]);
        for (int off = 16; off; off >>= 1) {
            unsigned long long o2 = __shfl_xor_sync(0xffffffffu, lmin, off);
            lmin = u64min_(lmin, o2);
        }
        if ((tid & 31) == 0) wmins[tid >> 5] = lmin;
        __syncthreads();
        if (tid == 0) {
            unsigned long long m = wmins[0];
            #pragma unroll
            for (int w = 1; w < 8; w++) m = u64min_(m, wmins[w]);
            int j = (int)(m & 0xffffffffull);
            float dv = __uint_as_float((unsigned int)(m >> 32));
            g_eidx[i * TOPK + sel] = j;
            g_dnb[i * TOPK + sel] = dv;
            out[OFF_EIDX + (size_t)i * TOPK + sel] = (float)j;
            out[OFF_EIDXSUB + (size_t)i * TOPK + sel] = (float)j;
            keys[j] = 0xffffffffffffffffull;
        }
        __syncthreads();
    }
}

// ---------------------------------------------------------------------------
// Shared LN epilogue: h[48 x 128] -> out
__device__ __forceinline__ void ln_epilogue(const float* __restrict__ h,
                                            const float* __restrict__ gg,
                                            const float* __restrict__ bb,
                                            float* __restrict__ out,
                                            size_t off, int i, int wid,
                                            int lane) {
    for (int k = wid; k < TOPK; k += 8) {
        float v0 = h[k * 128 + lane];
        float v1 = h[k * 128 + lane + 32];
        float v2 = h[k * 128 + lane + 64];
        float v3 = h[k * 128 + lane + 96];
        float s = v0 + v1 + v2 + v3;
        for (int o = 16; o; o >>= 1) s += __shfl_xor_sync(0xffffffffu, s, o);
        float mu = s * (1.0f / 128.0f);
        float d0 = v0 - mu, d1 = v1 - mu, d2 = v2 - mu, d3 = v3 - mu;
        float s2 = d0 * d0 + d1 * d1 + d2 * d2 + d3 * d3;
        for (int o = 16; o; o >>= 1) s2 += __shfl_xor_sync(0xffffffffu, s2, o);
        float inv = rsqrtf(s2 * (1.0f / 128.0f) + 1e-5f);
        size_t base = off + ((size_t)(i * TOPK + k)) * 128;
        out[base + lane]      = gg[lane]      * d0 * inv + bb[lane];
        out[base + lane + 32] = gg[lane + 32] * d1 * inv + bb[lane + 32];
        out[base + lane + 64] = gg[lane + 64] * d2 * inv + bb[lane + 64];
        out[base + lane + 96] = gg[lane + 96] * d3 * inv + bb[lane + 96];
    }
}

// ---------------------------------------------------------------------------
// Kernel 3: E via tf32 mma. M=48 (3 m16), N=128 (8 warps x 16), K=416
// (13 stages of 32). All A-tiles pre-generated into padded smem.
// smem floats: W0[4608] W1[4608] Aall[13*1728=22464]  => 126720 B total.
// ---------------------------------------------------------------------------
#define EW0 0
#define EW1 4608
#define EAA 9216
#define E_TOT (9216 + 13 * 1728)

__global__ void __launch_bounds__(256, 1) e_kernel(
    const float* __restrict__ Wpos, const float* __restrict__ bpos,
    const int* __restrict__ ridx, const int* __restrict__ clab,
    const float* __restrict__ ge, const float* __restrict__ be,
    float* __restrict__ out) {
    extern __shared__ float sm[];
    float* Aall = sm + EAA;
    int i = blockIdx.x;
    int tid = threadIdx.x;
    int wid = tid >> 5, lane = tid & 31;
    int g = lane >> 2, t = lane & 3;

    stage_ws_async(g_wer, EF, 0, sm + EW0, tid);
    cp_commit();

    // features: stage s tile = Aall + s*1728, row pitch 36
    if (tid < TOPK) {
        int k = tid;
        int j = g_eidx[i * TOPK + k];
        int offr = ridx[i] - ridx[j];
        int ec = (clab[i] == clab[j]) ? 1 : 0;
        int d = min(max(offr + 32, 0), 64) * ec + (1 - ec) * 65;
        float* fr = Aall + k * 36;   // stage 0, offsets 0..31
        #pragma unroll
        for (int f = 0; f < 16; f++) fr[f] = tf32f(Wpos[f * 66 + d] + bpos[f]);
        rbf_gen<16, true>(g_dnb[i * TOPK + k], 1.0f, fr + 16, E_SINV, E_D2,
                          E_E2);
    }

    const signed char pa[24] = {0,2,3,4,1,1,1,1,0,0,0,4,4,3,0,2,3,4,2,3,4,2,3,2};
    const signed char pb[24] = {0,2,3,4,0,2,3,4,2,3,4,2,3,2,1,1,1,1,0,0,0,4,4,3};
    for (int tt = tid; tt < TOPK * 24; tt += 256) {
        int k = tt / 24, p = tt - k * 24;
        int j = g_eidx[i * TOPK + k];
        const float* A = g_coords + i * 15 + (int)pa[p] * 3;
        const float* B = g_coords + j * 15 + (int)pb[p] * 3;
        float dx = A[0] - B[0], dy = A[1] - B[1], dz = A[2] - B[2];
        float D = sqrtf(dx * dx + dy * dy + dz * dz + 1e-6f);
        int f0 = 32 + p * 16;
        float* fr = Aall + (f0 >> 5) * 1728 + k * 36 + (f0 & 31);
        rbf_gen<16, true>(D, 1.0f, fr, E_SINV, E_D2, E_E2);
    }

    int n0 = wid * 16;
    float acc[3][2][4];
    #pragma unroll
    for (int mt = 0; mt < 3; mt++)
        #pragma unroll
        for (int j = 0; j < 2; j++)
            #pragma unroll
            for (int q = 0; q < 4; q++) acc[mt][j][q] = 0.0f;

    for (int st = 0; st < 13; st++) {
        cp_wait0();
        __syncthreads();
        if (st + 1 < 13) {
            stage_ws_async(g_wer, EF, st + 1, sm + ((st & 1) ? EW0 : EW1), tid);
            cp_commit();
        }
        const float* Wc = sm + ((st & 1) ? EW1 : EW0);
        const float* As = Aall + st * 1728;
        #pragma unroll
        for (int k8 = 0; k8 < 4; k8++) {
            int ko = k8 * 8;
            unsigned af[3][4];
            #pragma unroll
            for (int mt = 0; mt < 3; mt++) {
                const float* Ab = As + (mt * 16) * 36;
                af[mt][0] = __float_as_uint(Ab[g * 36 + ko + t]);
                af[mt][1] = __float_as_uint(Ab[(g + 8) * 36 + ko + t]);
                af[mt][2] = __float_as_uint(Ab[g * 36 + ko + t + 4]);
                af[mt][3] = __float_as_uint(Ab[(g + 8) * 36 + ko + t + 4]);
            }
            #pragma unroll
            for (int j = 0; j < 2; j++) {
                unsigned b0 = __float_as_uint(Wc[(n0 + 8 * j + g) * 36 + ko + t]);
                unsigned b1 =
                    __float_as_uint(Wc[(n0 + 8 * j + g) * 36 + ko + t + 4]);
                #pragma unroll
                for (int mt = 0; mt < 3; mt++)
                    mma_tf32(acc[mt][j][0], acc[mt][j][1], acc[mt][j][2],
                             acc[mt][j][3], af[mt][0], af[mt][1], af[mt][2],
                             af[mt][3], b0, b1);
            }
        }
    }
    __syncthreads();

    float* h = Aall;  // 48*128 floats
    #pragma unroll
    for (int mt = 0; mt < 3; mt++)
        #pragma unroll
        for (int j = 0; j < 2; j++) {
            int col = n0 + 8 * j + 2 * t;
            *(float2*)(h + (mt * 16 + g) * 128 + col) =
                make_float2(acc[mt][j][0], acc[mt][j][1]);
            *(float2*)(h + (mt * 16 + g + 8) * 128 + col) =
                make_float2(acc[mt][j][2], acc[mt][j][3]);
        }
    __syncthreads();

    ln_epilogue(h, ge, be, out, OFF_E, i, wid, lane);
}

// ---------------------------------------------------------------------------
// Kernel 4: E_s via tf32 mma (unchanged from R10).
// ---------------------------------------------------------------------------
#define ES_W0  0
#define ES_W1  4608
#define ES_A   9216
#define ES_SDV 10944
#define ES_SDG 18784
#define ES_TOT 26624

__global__ void __launch_bounds__(256, 2) es_kernel(
    const float* __restrict__ X, const float* __restrict__ amask,
    const float* __restrict__ gs, const float* __restrict__ bs,
    float* __restrict__ out) {
    extern __shared__ float sm[];
    float* Asm = sm + ES_A;
    float* SDv = sm + ES_SDV;
    float* SDg = sm + ES_SDG;
    __shared__ int jn[TOPK];
    __shared__ float anch[15];

    int i = blockIdx.x;
    int tid = threadIdx.x;
    int wid = tid >> 5, lane = tid & 31;
    int g = lane >> 2, t = lane & 3;

    stage_ws_async(g_wsr, SF, 0, sm + ES_W0, tid);
    cp_commit();

    if (tid < TOPK) jn[tid] = g_eidx[i * TOPK + tid];
    if (tid >= 64 && tid < 79) anch[tid - 64] = g_coords[i * 15 + (tid - 64)];
    __syncthreads();

    #pragma unroll
    for (int it = 0; it < 6; it++) {
        int task = tid + 256 * it;
        int e = task >> 5, s = task & 31;
        int j = jn[e];
        size_t bi = (size_t)j * 37 + 5 + s;
        float x0 = X[bi * 3 + 0], x1 = X[bi * 3 + 1], x2 = X[bi * 3 + 2];
        float m = amask[bi];
        #pragma unroll
        for (int a = 0; a < 5; a++) {
            float dx = anch[a * 3 + 0] - x0;
            float dy = anch[a * 3 + 1] - x1;
            float dz = anch[a * 3 + 2] - x2;
            float D = sqrtf(dx * dx + dy * dy + dz * dz + 1e-6f);
            float sc = (D - 2.0f) * S_SINV;
            float v = m * __expf(-S_D2 * sc * sc);
            float gg = __expf(S_D2 * (2.0f * sc - 1.0f));
            int cell = a * 32 + s;
            SDv[cell * 49 + e] = v;
            SDg[cell * 49 + e] = gg;
        }
    }
    __syncthreads();

    if (tid < 192) {
        int e = tid >> 2, c4 = tid & 3;
        float v = SDv[c4 * 49 + e];
        float gg = SDg[c4 * 49 + e];
        float vals[8];
        vals[0] = v;
        #pragma unroll
        for (int r = 1; r < 8; r++) { v *= gg; gg *= S_E2; vals[r] = v; }
        float4 f0, f1;
        f0.x = tf32f(vals[0]); f0.y = tf32f(vals[1]);
        f0.z = tf32f(vals[2]); f0.w = tf32f(vals[3]);
        f1.x = tf32f(vals[4]); f1.y = tf32f(vals[5]);
        f1.z = tf32f(vals[6]); f1.w = tf32f(vals[7]);
        *(float4*)(Asm + e * 36 + c4 * 8) = f0;
        *(float4*)(Asm + e * 36 + c4 * 8 + 4) = f1;
    }

    int n0 = wid * 16;
    float acc[3][2][4];
    #pragma unroll
    for (int mt = 0; mt < 3; mt++)
        #pragma unroll
        for (int j = 0; j < 2; j++)
            #pragma unroll
            for (int q = 0; q < 4; q++) acc[mt][j][q] = 0.0f;

    for (int st = 0; st < 40; st++) {
        cp_wait0();
        __syncthreads();
        if (st + 1 < 40) {
            stage_ws_async(g_wsr, SF, st + 1, sm + ((st & 1) ? ES_W0 : ES_W1),
                           tid);
            cp_commit();
        }
        const float* Wc = sm + ((st & 1) ? ES_W1 : ES_W0);
        #pragma unroll
        for (int k8 = 0; k8 < 4; k8++) {
            int ko = k8 * 8;
            unsigned af[3][4];
            #pragma unroll
            for (int mt = 0; mt < 3; mt++) {
                const float* Ab = Asm + (mt * 16) * 36;
                af[mt][0] = __float_as_uint(Ab[g * 36 + ko + t]);
                af[mt][1] = __float_as_uint(Ab[(g + 8) * 36 + ko + t]);
                af[mt][2] = __float_as_uint(Ab[g * 36 + ko + t + 4]);
                af[mt][3] = __float_as_uint(Ab[(g + 8) * 36 + ko + t + 4]);
            }
            #pragma unroll
            for (int j = 0; j < 2; j++) {
                unsigned b0 = __float_as_uint(Wc[(n0 + 8 * j + g) * 36 + ko + t]);
                unsigned b1 =
                    __float_as_uint(Wc[(n0 + 8 * j + g) * 36 + ko + t + 4]);
                #pragma unroll
                for (int mt = 0; mt < 3; mt++)
                    mma_tf32(acc[mt][j][0], acc[mt][j][1], acc[mt][j][2],
                             acc[mt][j][3], af[mt][0], af[mt][1], af[mt][2],
                             af[mt][3], b0, b1);
            }
        }
        __syncthreads();
        if (st + 1 < 40 && tid < 192) {
            int e = tid >> 2, c4 = tid & 3;
            int cell = 4 * (st + 1) + c4;
            float v = SDv[cell * 49 + e];
            float gg = SDg[cell * 49 + e];
            float vals[8];
            vals[0] = v;
            #pragma unroll
            for (int r = 1; r < 8; r++) { v *= gg; gg *= S_E2; vals[r] = v; }
            float4 f0, f1;
            f0.x = tf32f(vals[0]); f0.y = tf32f(vals[1]);
            f0.z = tf32f(vals[2]); f0.w = tf32f(vals[3]);
            f1.x = tf32f(vals[4]); f1.y = tf32f(vals[5]);
            f1.z = tf32f(vals[6]); f1.w = tf32f(vals[7]);
            *(float4*)(Asm + e * 36 + c4 * 8) = f0;
            *(float4*)(Asm + e * 36 + c4 * 8 + 4) = f1;
        }
    }
    __syncthreads();

    float* h = SDv;
    #pragma unroll
    for (int mt = 0; mt < 3; mt++)
        #pragma unroll
        for (int j = 0; j < 2; j++) {
            int col = n0 + 8 * j + 2 * t;
            *(float2*)(h + (mt * 16 + g) * 128 + col) =
                make_float2(acc[mt][j][0], acc[mt][j][1]);
            *(float2*)(h + (mt * 16 + g + 8) * 128 + col) =
                make_float2(acc[mt][j][2], acc[mt][j][3]);
        }
    __syncthreads();

    ln_epilogue(h, gs, bs, out, OFF_ES, i, wid, lane);
}

// ---------------------------------------------------------------------------
extern "C" void kernel_launch(void* const* d_in, const int* in_sizes, int n_in,
                              void* d_out, int out_size) {
    (void)in_sizes; (void)n_in; (void)out_size;
    const float* X     = (const float*)d_in[0];
    const float* mask  = (const float*)d_in[2];
    const float* amask = (const float*)d_in[3];
    const int*   ridx  = (const int*)d_in[4];
    const int*   clab  = (const int*)d_in[6];
    const float* Wpos  = (const float*)d_in[7];
    const float* bpos  = (const float*)d_in[8];
    const float* We    = (const float*)d_in[9];
    const float* ge    = (const float*)d_in[10];
    const float* be    = (const float*)d_in[11];
    const float* Ws    = (const float*)d_in[12];
    const float* gs    = (const float*)d_in[13];
    const float* bs    = (const float*)d_in[14];
    float* out = (float*)d_out;

    int e_smem  = E_TOT * 4;     // 126720
    int es_smem = ES_TOT * 4;    // 106496
    cudaFuncSetAttribute(e_kernel, cudaFuncAttributeMaxDynamicSharedMemorySize,
                         e_smem);
    cudaFuncSetAttribute(es_kernel, cudaFuncAttributeMaxDynamicSharedMemorySize,
                         es_smem);

    geom_kernel<<<(LRES + 255) / 256, 256>>>(X);
    wcvt_kernel<<<(128 * SF + 255) / 256, 256>>>(Ws, We);
    topk_kernel<<<LRES, 256>>>(X, mask, out);
    e_kernel<<<LRES, 256, e_smem>>>(Wpos, bpos, ridx, clab, ge, be, out);
    es_kernel<<<LRES, 256, es_smem>>>(X, amask, gs, bs, out);
}

// round 12
// speedup vs baseline: 2.9468x; 1.0760x over previous
#include <cuda_runtime.h>

#define LRES 1024
#define TOPK 48
#define EF   416
#define SF   1280

#define OFF_E       0ull
#define OFF_EIDX    6291456ull
#define OFF_ES      6340608ull
#define OFF_EIDXSUB 12632064ull

__device__ float g_coords[LRES * 15];
__device__ int   g_eidx[LRES * TOPK];
__device__ float g_dnb[LRES * TOPK];
__device__ float g_wsr[128 * SF];   // tf32-rounded W_s
__device__ float g_wer[128 * EF];   // tf32-rounded W_e

__device__ __forceinline__ unsigned long long u64min_(unsigned long long a,
                                                      unsigned long long b) {
    return a < b ? a : b;
}

__device__ __forceinline__ void cp_commit() {
    asm volatile("cp.async.commit_group;" ::: "memory");
}
__device__ __forceinline__ void cp_wait0() {
    asm volatile("cp.async.wait_group 0;" ::: "memory");
}

__device__ __forceinline__ unsigned cvt_tf32(float x) {
    unsigned u;
    asm("cvt.rna.tf32.f32 %0, %1;" : "=r"(u) : "f"(x));
    return u;
}
__device__ __forceinline__ float tf32f(float x) {
    return __uint_as_float(cvt_tf32(x));
}

__device__ __forceinline__ void mma_tf32(float& d0, float& d1, float& d2,
                                         float& d3, unsigned a0, unsigned a1,
                                         unsigned a2, unsigned a3, unsigned b0,
                                         unsigned b1) {
    asm volatile(
        "mma.sync.aligned.m16n8k8.row.col.f32.tf32.tf32.f32 "
        "{%0,%1,%2,%3}, {%4,%5,%6,%7}, {%8,%9}, {%0,%1,%2,%3};"
        : "+f"(d0), "+f"(d1), "+f"(d2), "+f"(d3)
        : "r"(a0), "r"(a1), "r"(a2), "r"(a3), "r"(b0), "r"(b1));
}

// Chained RBF; ROUND -> store tf32-rounded values.
template <int NB, bool ROUND>
__device__ __forceinline__ void rbf_gen(float D, float m, float* __restrict__ fr,
                                        float SINV, float D2, float E2c) {
    float s = (D - 2.0f) * SINV;
    float v = __expf(-D2 * s * s);
    float g = __expf(D2 * (2.0f * s - 1.0f));
    float vals[NB];
    vals[0] = v;
    #pragma unroll
    for (int r = 1; r < NB; r++) { v *= g; g *= E2c; vals[r] = v; }
    if (vals[0] < 1e-30f) {
        float sN = s - (float)(NB - 1);
        float v1 = __expf(-D2 * sN * sN);
        float g1 = __expf(-D2 * (2.0f * sN + 1.0f));
        vals[NB - 1] = fmaxf(vals[NB - 1], v1);
        #pragma unroll
        for (int r = NB - 2; r >= 0; r--) {
            v1 *= g1; g1 *= E2c;
            vals[r] = fmaxf(vals[r], v1);
        }
    }
    #pragma unroll
    for (int r = 0; r < NB; r++)
        fr[r] = ROUND ? tf32f(m * vals[r]) : m * vals[r];
}

#define E_SINV 0.75f
#define E_D2   1.13777778f
#define E_E2   0.10273980f
#define S_SINV 0.35f
#define S_D2   1.30612245f
#define S_E2   0.07336966f

// stage 128ch x 32feat fp32 tile -> Wsm[ch*36 + f], 16B cp.async
__device__ __forceinline__ void stage_ws_async(const float* __restrict__ Wsrc,
                                               int stride, int st,
                                               float* __restrict__ Wsm,
                                               int tid) {
    #pragma unroll
    for (int p = tid; p < 1024; p += 256) {
        int ch = p >> 3, fc = p & 7;
        const float* src = Wsrc + ch * stride + st * 32 + fc * 4;
        unsigned int dst =
            (unsigned int)__cvta_generic_to_shared(Wsm + ch * 36 + fc * 4);
        asm volatile("cp.async.ca.shared.global [%0], [%1], 16;"
                     :: "r"(dst), "l"(src) : "memory");
    }
}

// ---------------------------------------------------------------------------
__global__ void wcvt_kernel(const float* __restrict__ Ws,
                            const float* __restrict__ We) {
    int i = blockIdx.x * 256 + threadIdx.x;
    if (i < 128 * SF) g_wsr[i] = tf32f(Ws[i]);
    if (i < 128 * EF) g_wer[i] = tf32f(We[i]);
}

// ---------------------------------------------------------------------------
__global__ void geom_kernel(const float* __restrict__ X) {
    int i = blockIdx.x * blockDim.x + threadIdx.x;
    if (i >= LRES) return;
    const float* xi = X + (size_t)i * 37 * 3;
    float n0 = xi[0],  n1 = xi[1],  n2 = xi[2];
    float a0 = xi[3],  a1 = xi[4],  a2 = xi[5];
    float c0 = xi[6],  c1 = xi[7],  c2 = xi[8];
    float o0 = xi[12], o1 = xi[13], o2 = xi[14];
    float b0 = a0 - n0, b1 = a1 - n1, b2 = a2 - n2;
    float d0 = c0 - a0, d1 = c1 - a1, d2 = c2 - a2;
    float x0 = b1 * d2 - b2 * d1;
    float x1 = b2 * d0 - b0 * d2;
    float x2 = b0 * d1 - b1 * d0;
    float cb0 = -0.58273431f * x0 + 0.56802827f * b0 - 0.54067466f * d0 + a0;
    float cb1 = -0.58273431f * x1 + 0.56802827f * b1 - 0.54067466f * d1 + a1;
    float cb2 = -0.58273431f * x2 + 0.56802827f * b2 - 0.54067466f * d2 + a2;
    float* dst = g_coords + i * 15;
    dst[0] = n0;  dst[1] = n1;  dst[2] = n2;
    dst[3] = a0;  dst[4] = a1;  dst[5] = a2;
    dst[6] = c0;  dst[7] = c1;  dst[8] = c2;
    dst[9] = o0;  dst[10] = o1; dst[11] = o2;
    dst[12] = cb0; dst[13] = cb1; dst[14] = cb2;
}

// ---------------------------------------------------------------------------
__global__ void topk_kernel(const float* __restrict__ X,
                            const float* __restrict__ mask,
                            float* __restrict__ out) {
    __shared__ float dsh[LRES];
    __shared__ unsigned long long keys[LRES];
    __shared__ float wmaxs[8];
    __shared__ unsigned long long wmins[8];
    __shared__ float smDmax;

    int i = blockIdx.x;
    int tid = threadIdx.x;
    float cax = X[((size_t)i * 37 + 1) * 3 + 0];
    float cay = X[((size_t)i * 37 + 1) * 3 + 1];
    float caz = X[((size_t)i * 37 + 1) * 3 + 2];
    float mi = mask[i];

    float lmax = 0.0f;
    for (int j = tid; j < LRES; j += 256) {
        float dx = cax - X[((size_t)j * 37 + 1) * 3 + 0];
        float dy = cay - X[((size_t)j * 37 + 1) * 3 + 1];
        float dz = caz - X[((size_t)j * 37 + 1) * 3 + 2];
        float s = dx * dx + dy * dy + dz * dz;
        float m2 = mi * mask[j];
        float Dv = m2 * sqrtf(s + 1e-6f);
        dsh[j] = Dv;
        lmax = fmaxf(lmax, Dv);
    }
    for (int off = 16; off; off >>= 1)
        lmax = fmaxf(lmax, __shfl_xor_sync(0xffffffffu, lmax, off));
    if ((tid & 31) == 0) wmaxs[tid >> 5] = lmax;
    __syncthreads();
    if (tid == 0) {
        float m = wmaxs[0];
        #pragma unroll
        for (int w = 1; w < 8; w++) m = fmaxf(m, wmaxs[w]);
        smDmax = m;
    }
    __syncthreads();
    float Dmax = smDmax;

    for (int j = tid; j < LRES; j += 256) {
        float m2 = mi * mask[j];
        float Dadj = dsh[j] + (1.0f - m2) * Dmax;
        keys[j] = (((unsigned long long)__float_as_uint(Dadj)) << 32) |
                  (unsigned int)j;
    }
    __syncthreads();

    for (int sel = 0; sel < TOPK; sel++) {
        unsigned long long lmin = 0xffffffffffffffffull;
        #pragma unroll
        for (int c = 0; c < 4; c++) lmin = u64min_(lmin, keys[tid + 256 * c]);
        for (int off = 16; off; off >>= 1) {
            unsigned long long o2 = __shfl_xor_sync(0xffffffffu, lmin, off);
            lmin = u64min_(lmin, o2);
        }
        if ((tid & 31) == 0) wmins[tid >> 5] = lmin;
        __syncthreads();
        if (tid == 0) {
            unsigned long long m = wmins[0];
            #pragma unroll
            for (int w = 1; w < 8; w++) m = u64min_(m, wmins[w]);
            int j = (int)(m & 0xffffffffull);
            float dv = __uint_as_float((unsigned int)(m >> 32));
            g_eidx[i * TOPK + sel] = j;
            g_dnb[i * TOPK + sel] = dv;
            out[OFF_EIDX + (size_t)i * TOPK + sel] = (float)j;
            out[OFF_EIDXSUB + (size_t)i * TOPK + sel] = (float)j;
            keys[j] = 0xffffffffffffffffull;
        }
        __syncthreads();
    }
}

// ---------------------------------------------------------------------------
// Shared LN epilogue: h[48 x 128] -> out
__device__ __forceinline__ void ln_epilogue(const float* __restrict__ h,
                                            const float* __restrict__ gg,
                                            const float* __restrict__ bb,
                                            float* __restrict__ out,
                                            size_t off, int i, int wid,
                                            int lane) {
    for (int k = wid; k < TOPK; k += 8) {
        float v0 = h[k * 128 + lane];
        float v1 = h[k * 128 + lane + 32];
        float v2 = h[k * 128 + lane + 64];
        float v3 = h[k * 128 + lane + 96];
        float s = v0 + v1 + v2 + v3;
        for (int o = 16; o; o >>= 1) s += __shfl_xor_sync(0xffffffffu, s, o);
        float mu = s * (1.0f / 128.0f);
        float d0 = v0 - mu, d1 = v1 - mu, d2 = v2 - mu, d3 = v3 - mu;
        float s2 = d0 * d0 + d1 * d1 + d2 * d2 + d3 * d3;
        for (int o = 16; o; o >>= 1) s2 += __shfl_xor_sync(0xffffffffu, s2, o);
        float inv = rsqrtf(s2 * (1.0f / 128.0f) + 1e-5f);
        size_t base = off + ((size_t)(i * TOPK + k)) * 128;
        out[base + lane]      = gg[lane]      * d0 * inv + bb[lane];
        out[base + lane + 32] = gg[lane + 32] * d1 * inv + bb[lane + 32];
        out[base + lane + 64] = gg[lane + 64] * d2 * inv + bb[lane + 64];
        out[base + lane + 96] = gg[lane + 96] * d3 * inv + bb[lane + 96];
    }
}

// ---------------------------------------------------------------------------
// Kernel 3: E via tf32 mma, streaming A tiles. M=48, N=128, K=416
// (13 stages of 32). Seeds = pair distances; A double-buffered; 1 sync/stage.
// smem floats: W0[4608] W1[4608] A0[1728] A1[1728] SD[1176] = 13848 (55392 B)
// ---------------------------------------------------------------------------
#define EW0 0
#define EW1 4608
#define EA0 9216
#define EA1 10944
#define ESD 12672
#define E_TOT 13848

__global__ void __launch_bounds__(256, 2) e_kernel(
    const float* __restrict__ Wpos, const float* __restrict__ bpos,
    const int* __restrict__ ridx, const int* __restrict__ clab,
    const float* __restrict__ ge, const float* __restrict__ be,
    float* __restrict__ out) {
    extern __shared__ float sm[];
    float* SD = sm + ESD;
    int i = blockIdx.x;
    int tid = threadIdx.x;
    int wid = tid >> 5, lane = tid & 31;
    int g = lane >> 2, t = lane & 3;

    stage_ws_async(g_wer, EF, 0, sm + EW0, tid);
    cp_commit();

    // stage 0 A-tile: pos16 + rbf16(Dnb)
    if (tid < TOPK) {
        int k = tid;
        int j = g_eidx[i * TOPK + k];
        int offr = ridx[i] - ridx[j];
        int ec = (clab[i] == clab[j]) ? 1 : 0;
        int d = min(max(offr + 32, 0), 64) * ec + (1 - ec) * 65;
        float* fr = sm + EA0 + k * 36;
        #pragma unroll
        for (int f = 0; f < 16; f++) fr[f] = tf32f(Wpos[f * 66 + d] + bpos[f]);
        rbf_gen<16, true>(g_dnb[i * TOPK + k], 1.0f, fr + 16, E_SINV, E_D2,
                          E_E2);
    }

    // seeds: distances for 48 edges x 24 pairs
    const signed char pa[24] = {0,2,3,4,1,1,1,1,0,0,0,4,4,3,0,2,3,4,2,3,4,2,3,2};
    const signed char pb[24] = {0,2,3,4,0,2,3,4,2,3,4,2,3,2,1,1,1,1,0,0,0,4,4,3};
    for (int tt = tid; tt < TOPK * 24; tt += 256) {
        int k = tt / 24, p = tt - k * 24;
        int j = g_eidx[i * TOPK + k];
        const float* A = g_coords + i * 15 + (int)pa[p] * 3;
        const float* B = g_coords + j * 15 + (int)pb[p] * 3;
        float dx = A[0] - B[0], dy = A[1] - B[1], dz = A[2] - B[2];
        SD[p * 49 + k] = sqrtf(dx * dx + dy * dy + dz * dz + 1e-6f);
    }

    int n0 = wid * 16;
    float acc[3][2][4];
    #pragma unroll
    for (int mt = 0; mt < 3; mt++)
        #pragma unroll
        for (int j = 0; j < 2; j++)
            #pragma unroll
            for (int q = 0; q < 4; q++) acc[mt][j][q] = 0.0f;

    for (int st = 0; st < 13; st++) {
        cp_wait0();
        __syncthreads();
        if (st + 1 < 13) {
            stage_ws_async(g_wer, EF, st + 1,
                           sm + (((st + 1) & 1) ? EW1 : EW0), tid);
            cp_commit();
        }
        const float* Wc = sm + ((st & 1) ? EW1 : EW0);
        const float* As = sm + ((st & 1) ? EA1 : EA0);
        #pragma unroll
        for (int k8 = 0; k8 < 4; k8++) {
            int ko = k8 * 8;
            unsigned af[3][4];
            #pragma unroll
            for (int mt = 0; mt < 3; mt++) {
                const float* Ab = As + (mt * 16) * 36;
                af[mt][0] = __float_as_uint(Ab[g * 36 + ko + t]);
                af[mt][1] = __float_as_uint(Ab[(g + 8) * 36 + ko + t]);
                af[mt][2] = __float_as_uint(Ab[g * 36 + ko + t + 4]);
                af[mt][3] = __float_as_uint(Ab[(g + 8) * 36 + ko + t + 4]);
            }
            #pragma unroll
            for (int j = 0; j < 2; j++) {
                unsigned b0 = __float_as_uint(Wc[(n0 + 8 * j + g) * 36 + ko + t]);
                unsigned b1 =
                    __float_as_uint(Wc[(n0 + 8 * j + g) * 36 + ko + t + 4]);
                #pragma unroll
                for (int mt = 0; mt < 3; mt++)
                    mma_tf32(acc[mt][j][0], acc[mt][j][1], acc[mt][j][2],
                             acc[mt][j][3], af[mt][0], af[mt][1], af[mt][2],
                             af[mt][3], b0, b1);
            }
        }
        // expand stage st+1 (pairs 2st, 2st+1) into the other A buffer
        if (st + 1 < 13 && tid < 96) {
            int e = tid >> 1, pp = tid & 1;
            int p = 2 * st + pp;
            float D = SD[p * 49 + e];
            float* fr = sm + (((st + 1) & 1) ? EA1 : EA0) + e * 36 + pp * 16;
            rbf_gen<16, true>(D, 1.0f, fr, E_SINV, E_D2, E_E2);
        }
    }
    __syncthreads();

    float* h = sm;  // aliases W buffers (done with them)
    #pragma unroll
    for (int mt = 0; mt < 3; mt++)
        #pragma unroll
        for (int j = 0; j < 2; j++) {
            int col = n0 + 8 * j + 2 * t;
            *(float2*)(h + (mt * 16 + g) * 128 + col) =
                make_float2(acc[mt][j][0], acc[mt][j][1]);
            *(float2*)(h + (mt * 16 + g + 8) * 128 + col) =
                make_float2(acc[mt][j][2], acc[mt][j][3]);
        }
    __syncthreads();

    ln_epilogue(h, ge, be, out, OFF_E, i, wid, lane);
}

// ---------------------------------------------------------------------------
// Kernel 4: E_s via tf32 mma, A double-buffered, 1 sync/stage.
// smem floats: W0[4608] W1[4608] A0[1728] A1[1728] SDv[7840] SDg[7840]
//            = 28352 floats (113408 B); h aliases SDv.
// ---------------------------------------------------------------------------
#define ES_W0  0
#define ES_W1  4608
#define ES_A0  9216
#define ES_A1  10944
#define ES_SDV 12672
#define ES_SDG 20512
#define ES_TOT 28352

__global__ void __launch_bounds__(256, 2) es_kernel(
    const float* __restrict__ X, const float* __restrict__ amask,
    const float* __restrict__ gs, const float* __restrict__ bs,
    float* __restrict__ out) {
    extern __shared__ float sm[];
    float* SDv = sm + ES_SDV;
    float* SDg = sm + ES_SDG;
    __shared__ int jn[TOPK];
    __shared__ float anch[15];

    int i = blockIdx.x;
    int tid = threadIdx.x;
    int wid = tid >> 5, lane = tid & 31;
    int g = lane >> 2, t = lane & 3;

    stage_ws_async(g_wsr, SF, 0, sm + ES_W0, tid);
    cp_commit();

    if (tid < TOPK) jn[tid] = g_eidx[i * TOPK + tid];
    if (tid >= 64 && tid < 79) anch[tid - 64] = g_coords[i * 15 + (tid - 64)];
    __syncthreads();

    #pragma unroll
    for (int it = 0; it < 6; it++) {
        int task = tid + 256 * it;
        int e = task >> 5, s = task & 31;
        int j = jn[e];
        size_t bi = (size_t)j * 37 + 5 + s;
        float x0 = X[bi * 3 + 0], x1 = X[bi * 3 + 1], x2 = X[bi * 3 + 2];
        float m = amask[bi];
        #pragma unroll
        for (int a = 0; a < 5; a++) {
            float dx = anch[a * 3 + 0] - x0;
            float dy = anch[a * 3 + 1] - x1;
            float dz = anch[a * 3 + 2] - x2;
            float D = sqrtf(dx * dx + dy * dy + dz * dz + 1e-6f);
            float sc = (D - 2.0f) * S_SINV;
            float v = m * __expf(-S_D2 * sc * sc);
            float gg = __expf(S_D2 * (2.0f * sc - 1.0f));
            int cell = a * 32 + s;
            SDv[cell * 49 + e] = v;
            SDg[cell * 49 + e] = gg;
        }
    }
    __syncthreads();

    // expansion for stage 0 into A0
    if (tid < 192) {
        int e = tid >> 2, c4 = tid & 3;
        float v = SDv[c4 * 49 + e];
        float gg = SDg[c4 * 49 + e];
        float vals[8];
        vals[0] = v;
        #pragma unroll
        for (int r = 1; r < 8; r++) { v *= gg; gg *= S_E2; vals[r] = v; }
        float4 f0, f1;
        f0.x = tf32f(vals[0]); f0.y = tf32f(vals[1]);
        f0.z = tf32f(vals[2]); f0.w = tf32f(vals[3]);
        f1.x = tf32f(vals[4]); f1.y = tf32f(vals[5]);
        f1.z = tf32f(vals[6]); f1.w = tf32f(vals[7]);
        *(float4*)(sm + ES_A0 + e * 36 + c4 * 8) = f0;
        *(float4*)(sm + ES_A0 + e * 36 + c4 * 8 + 4) = f1;
    }

    int n0 = wid * 16;
    float acc[3][2][4];
    #pragma unroll
    for (int mt = 0; mt < 3; mt++)
        #pragma unroll
        for (int j = 0; j < 2; j++)
            #pragma unroll
            for (int q = 0; q < 4; q++) acc[mt][j][q] = 0.0f;

    for (int st = 0; st < 40; st++) {
        cp_wait0();
        __syncthreads();
        if (st + 1 < 40) {
            stage_ws_async(g_wsr, SF, st + 1,
                           sm + (((st + 1) & 1) ? ES_W1 : ES_W0), tid);
            cp_commit();
        }
        const float* Wc = sm + ((st & 1) ? ES_W1 : ES_W0);
        const float* As = sm + ((st & 1) ? ES_A1 : ES_A0);
        #pragma unroll
        for (int k8 = 0; k8 < 4; k8++) {
            int ko = k8 * 8;
            unsigned af[3][4];
            #pragma unroll
            for (int mt = 0; mt < 3; mt++) {
                const float* Ab = As + (mt * 16) * 36;
                af[mt][0] = __float_as_uint(Ab[g * 36 + ko + t]);
                af[mt][1] = __float_as_uint(Ab[(g + 8) * 36 + ko + t]);
                af[mt][2] = __float_as_uint(Ab[g * 36 + ko + t + 4]);
                af[mt][3] = __float_as_uint(Ab[(g + 8) * 36 + ko + t + 4]);
            }
            #pragma unroll
            for (int j = 0; j < 2; j++) {
                unsigned b0 = __float_as_uint(Wc[(n0 + 8 * j + g) * 36 + ko + t]);
                unsigned b1 =
                    __float_as_uint(Wc[(n0 + 8 * j + g) * 36 + ko + t + 4]);
                #pragma unroll
                for (int mt = 0; mt < 3; mt++)
                    mma_tf32(acc[mt][j][0], acc[mt][j][1], acc[mt][j][2],
                             acc[mt][j][3], af[mt][0], af[mt][1], af[mt][2],
                             af[mt][3], b0, b1);
            }
        }
        // expand stage st+1 into the other A buffer (overlaps mma)
        if (st + 1 < 40 && tid < 192) {
            int e = tid >> 2, c4 = tid & 3;
            int cell = 4 * (st + 1) + c4;
            float v = SDv[cell * 49 + e];
            float gg = SDg[cell * 49 + e];
            float vals[8];
            vals[0] = v;
            #pragma unroll
            for (int r = 1; r < 8; r++) { v *= gg; gg *= S_E2; vals[r] = v; }
            float4 f0, f1;
            f0.x = tf32f(vals[0]); f0.y = tf32f(vals[1]);
            f0.z = tf32f(vals[2]); f0.w = tf32f(vals[3]);
            f1.x = tf32f(vals[4]); f1.y = tf32f(vals[5]);
            f1.z = tf32f(vals[6]); f1.w = tf32f(vals[7]);
            float* An = sm + (((st + 1) & 1) ? ES_A1 : ES_A0);
            *(float4*)(An + e * 36 + c4 * 8) = f0;
            *(float4*)(An + e * 36 + c4 * 8 + 4) = f1;
        }
    }
    __syncthreads();

    float* h = SDv;
    #pragma unroll
    for (int mt = 0; mt < 3; mt++)
        #pragma unroll
        for (int j = 0; j < 2; j++) {
            int col = n0 + 8 * j + 2 * t;
            *(float2*)(h + (mt * 16 + g) * 128 + col) =
                make_float2(acc[mt][j][0], acc[mt][j][1]);
            *(float2*)(h + (mt * 16 + g + 8) * 128 + col) =
                make_float2(acc[mt][j][2], acc[mt][j][3]);
        }
    __syncthreads();

    ln_epilogue(h, gs, bs, out, OFF_ES, i, wid, lane);
}

// ---------------------------------------------------------------------------
extern "C" void kernel_launch(void* const* d_in, const int* in_sizes, int n_in,
                              void* d_out, int out_size) {
    (void)in_sizes; (void)n_in; (void)out_size;
    const float* X     = (const float*)d_in[0];
    const float* mask  = (const float*)d_in[2];
    const float* amask = (const float*)d_in[3];
    const int*   ridx  = (const int*)d_in[4];
    const int*   clab  = (const int*)d_in[6];
    const float* Wpos  = (const float*)d_in[7];
    const float* bpos  = (const float*)d_in[8];
    const float* We    = (const float*)d_in[9];
    const float* ge    = (const float*)d_in[10];
    const float* be    = (const float*)d_in[11];
    const float* Ws    = (const float*)d_in[12];
    const float* gs    = (const float*)d_in[13];
    const float* bs    = (const float*)d_in[14];
    float* out = (float*)d_out;

    int e_smem  = E_TOT * 4;     // 55392
    int es_smem = ES_TOT * 4;    // 113408
    cudaFuncSetAttribute(e_kernel, cudaFuncAttributeMaxDynamicSharedMemorySize,
                         e_smem);
    cudaFuncSetAttribute(es_kernel, cudaFuncAttributeMaxDynamicSharedMemorySize,
                         es_smem);

    geom_kernel<<<(LRES + 255) / 256, 256>>>(X);
    wcvt_kernel<<<(128 * SF + 255) / 256, 256>>>(Ws, We);
    topk_kernel<<<LRES, 256>>>(X, mask, out);
    e_kernel<<<LRES, 256, e_smem>>>(Wpos, bpos, ridx, clab, ge, be, out);
    es_kernel<<<LRES, 256, es_smem>>>(X, amask, gs, bs, out);
}